// round 14
// baseline (speedup 1.0000x reference)
#include <cuda_runtime.h>
#include <math.h>
#include <stdint.h>

// ---------------------------------------------------------------------------
// VQ-VAE forward, fp32 direct kernels.
// Output layout (concatenated, float32): out | z | e_k | ids
// ENCODER + VQ ARITHMETIC IS FROZEN (bit-load-bearing for ids). Only data
// movement (smem layouts, vector loads) may change there.
// ---------------------------------------------------------------------------

static const size_t OUT_OFF = 0;
static const size_t Z_OFF   = (size_t)32 * 3 * 256 * 256;
static const size_t EK_OFF  = Z_OFF + (size_t)32 * 256 * 32 * 32;
static const size_t IDS_OFF = EK_OFF + (size_t)32 * 256 * 32 * 32;

__device__ __align__(16) float g_bufA[(size_t)32 * 64 * 128 * 128];
__device__ __align__(16) float g_bufB[(size_t)32 * 128 * 64 * 64];
__device__ __align__(16) float g_ct[256 * 1024];     // codebook^T [d][code]
__device__ __align__(16) double g_cnorm_d[1024];     // exact norms (phase A keys)
__device__ __align__(16) float g_cnorm_f[1024];      // XLA-warp-order fp32 norms
__device__ int g_ids[32 * 1024];
__device__ int g_nflag;
__device__ int g_flagrows[16384];

#define POS_INF_F __int_as_float(0x7f800000)

// ---------------------------------------------------------------------------
// Conv2d k=3 s=2 p=1, NCHW, optional ReLU.
// Per-thread accumulation order (FROZEN): single accumulator per co, pure
// (kh, kw, ci) ascending. R13 change: weights staged co-fastest in smem,
// loaded as float4 -> 1 LDS.128 per 4 FFMA instead of 1 scalar LDS per FFMA.
// ---------------------------------------------------------------------------
template <int CIN, int COUT, int HIN, int COB, int TH, int TW, bool RELU>
__global__ void __launch_bounds__(128) conv_s2(const float* __restrict__ in,
                                               const float* __restrict__ w,
                                               float* __restrict__ out) {
    constexpr int HOUT = HIN / 2;
    constexpr int WOUT = HIN / 2;
    static_assert(COB % 4 == 0, "COB must be multiple of 4");
    __shared__ __align__(16) float ws[9 * CIN * COB];   // [k][ci][co]

    const int n   = blockIdx.y;
    const int cob = blockIdx.z * COB;
    const int tid = threadIdx.x;
    const int ty  = tid / TW;
    const int tx  = tid % TW;
    const int oh  = blockIdx.x * TH + ty;
    const int ow  = tx;

    const float* inB = in + (size_t)n * CIN * HIN * HIN;

    for (int i = tid; i < COB * CIN * 9; i += TH * TW) {
        int co = i / (CIN * 9);
        int r  = i % (CIN * 9);
        int ci = r / 9;
        int k  = r % 9;
        ws[(k * CIN + ci) * COB + co] = w[(size_t)(cob + co) * CIN * 9 + ci * 9 + k];
    }
    __syncthreads();

    float acc[COB];
#pragma unroll
    for (int i = 0; i < COB; i++) acc[i] = 0.f;

#pragma unroll
    for (int kh = 0; kh < 3; kh++) {
        int ih = 2 * oh - 1 + kh;
        if ((unsigned)ih >= (unsigned)HIN) continue;
#pragma unroll
        for (int kw = 0; kw < 3; kw++) {
            int iw = 2 * ow - 1 + kw;
            if ((unsigned)iw >= (unsigned)HIN) continue;
            const int k = kh * 3 + kw;
            const float* bp = inB + (size_t)ih * HIN + iw;
            const float* wk = &ws[k * CIN * COB];
#pragma unroll 4
            for (int ci = 0; ci < CIN; ci++) {
                float xv = __ldg(bp + (size_t)ci * HIN * HIN);
#pragma unroll
                for (int c4 = 0; c4 < COB / 4; c4++) {
                    float4 wv = *reinterpret_cast<const float4*>(&wk[ci * COB + c4 * 4]);
                    acc[c4 * 4 + 0] = fmaf(xv, wv.x, acc[c4 * 4 + 0]);
                    acc[c4 * 4 + 1] = fmaf(xv, wv.y, acc[c4 * 4 + 1]);
                    acc[c4 * 4 + 2] = fmaf(xv, wv.z, acc[c4 * 4 + 2]);
                    acc[c4 * 4 + 3] = fmaf(xv, wv.w, acc[c4 * 4 + 3]);
                }
            }
        }
    }

    float* o = out + ((size_t)n * COUT + cob) * HOUT * WOUT + (size_t)oh * WOUT + ow;
#pragma unroll
    for (int co = 0; co < COB; co++) {
        float v = acc[co];
        if (RELU) v = fmaxf(v, 0.f);
        o[(size_t)co * HOUT * WOUT] = v;
    }
}

// ---------------------------------------------------------------------------
// ConvTranspose2d k=3 s=2 p=1 outpad=1, vectorized weights (COB % 4 == 0).
// ACT: 0 = relu, 1 = sigmoid. Decoder precision does not affect ids.
// Weights staged [ci][k][co] -> float4 across co: 1 LDS.128 per 4 FFMA.
// ---------------------------------------------------------------------------
template <int CIN, int COUT, int HIN, int COB, int TH, int TW, int CISTEP, int ACT>
__global__ void __launch_bounds__(128) deconv_s2_v(const float* __restrict__ in,
                                                   const float* __restrict__ w,
                                                   float* __restrict__ out) {
    constexpr int HOUT = HIN * 2;
    static_assert(COB % 4 == 0, "COB must be multiple of 4");
    __shared__ __align__(16) float ws[CISTEP * 9 * COB];   // [ci][k][co]

    const int n   = blockIdx.y;
    const int cob = blockIdx.z * COB;
    const int tid = threadIdx.x;
    const int ty  = tid / TW;
    const int tx  = tid % TW;
    const int a   = blockIdx.x * TH + ty;
    const int b   = tx;

    const float* inB = in + (size_t)n * CIN * HIN * HIN;

    float acc[COB][4];
#pragma unroll
    for (int i = 0; i < COB; i++)
#pragma unroll
        for (int q = 0; q < 4; q++) acc[i][q] = 0.f;

    const bool bOK = (b + 1 < HIN);
    const bool aOK = (a + 1 < HIN);

    for (int ci0 = 0; ci0 < CIN; ci0 += CISTEP) {
        __syncthreads();
        for (int i = tid; i < COB * CISTEP * 9; i += TH * TW) {
            int co = i / (CISTEP * 9);
            int r  = i % (CISTEP * 9);
            int ci = r / 9;
            int k  = r % 9;
            ws[(ci * 9 + k) * COB + co] = w[(size_t)(cob + co) * CIN * 9 + (ci0 + ci) * 9 + k];
        }
        __syncthreads();

#pragma unroll
        for (int ci = 0; ci < CISTEP; ci++) {
            const float* p = inB + (size_t)(ci0 + ci) * HIN * HIN + (size_t)a * HIN + b;
            float v00 = __ldg(p);
            float v01 = bOK ? __ldg(p + 1) : 0.f;
            float v10 = aOK ? __ldg(p + HIN) : 0.f;
            float v11 = (aOK && bOK) ? __ldg(p + HIN + 1) : 0.f;
            const float* wb = &ws[ci * 9 * COB];
#pragma unroll
            for (int c4 = 0; c4 < COB / 4; c4++) {
                float4 w0 = *reinterpret_cast<const float4*>(&wb[0 * COB + c4 * 4]);
                float4 w1 = *reinterpret_cast<const float4*>(&wb[1 * COB + c4 * 4]);
                float4 w2 = *reinterpret_cast<const float4*>(&wb[2 * COB + c4 * 4]);
                float4 w3 = *reinterpret_cast<const float4*>(&wb[3 * COB + c4 * 4]);
                float4 w4 = *reinterpret_cast<const float4*>(&wb[4 * COB + c4 * 4]);
                float4 w5 = *reinterpret_cast<const float4*>(&wb[5 * COB + c4 * 4]);
                float4 w6 = *reinterpret_cast<const float4*>(&wb[6 * COB + c4 * 4]);
                float4 w7 = *reinterpret_cast<const float4*>(&wb[7 * COB + c4 * 4]);
                float4 w8 = *reinterpret_cast<const float4*>(&wb[8 * COB + c4 * 4]);
                const float wk0[4] = {w0.x, w0.y, w0.z, w0.w};
                const float wk1[4] = {w1.x, w1.y, w1.z, w1.w};
                const float wk2[4] = {w2.x, w2.y, w2.z, w2.w};
                const float wk3[4] = {w3.x, w3.y, w3.z, w3.w};
                const float wk4[4] = {w4.x, w4.y, w4.z, w4.w};
                const float wk5[4] = {w5.x, w5.y, w5.z, w5.w};
                const float wk6[4] = {w6.x, w6.y, w6.z, w6.w};
                const float wk7[4] = {w7.x, w7.y, w7.z, w7.w};
                const float wk8[4] = {w8.x, w8.y, w8.z, w8.w};
#pragma unroll
                for (int l = 0; l < 4; l++) {
                    int co = c4 * 4 + l;
                    acc[co][0] = fmaf(v00, wk4[l], acc[co][0]);
                    acc[co][1] = fmaf(v00, wk3[l], fmaf(v01, wk5[l], acc[co][1]));
                    acc[co][2] = fmaf(v00, wk1[l], fmaf(v10, wk7[l], acc[co][2]));
                    acc[co][3] = fmaf(v00, wk0[l],
                                 fmaf(v01, wk2[l],
                                 fmaf(v10, wk6[l],
                                 fmaf(v11, wk8[l], acc[co][3]))));
                }
            }
        }
    }

#pragma unroll
    for (int co = 0; co < COB; co++) {
        float r0, r1, r2, r3;
        if (ACT == 0) {
            r0 = fmaxf(acc[co][0], 0.f);
            r1 = fmaxf(acc[co][1], 0.f);
            r2 = fmaxf(acc[co][2], 0.f);
            r3 = fmaxf(acc[co][3], 0.f);
        } else {
            r0 = 1.f / (1.f + expf(-acc[co][0]));
            r1 = 1.f / (1.f + expf(-acc[co][1]));
            r2 = 1.f / (1.f + expf(-acc[co][2]));
            r3 = 1.f / (1.f + expf(-acc[co][3]));
        }
        float* o = out + ((size_t)n * COUT + cob + co) * HOUT * HOUT +
                   (size_t)(2 * a) * HOUT + 2 * b;
        *reinterpret_cast<float2*>(o)        = make_float2(r0, r1);
        *reinterpret_cast<float2*>(o + HOUT) = make_float2(r2, r3);
    }
}

// Scalar deconv (for COUT=3 final layer).
template <int CIN, int COUT, int HIN, int COB, int TH, int TW, int CISTEP, int ACT>
__global__ void __launch_bounds__(128) deconv_s2(const float* __restrict__ in,
                                                 const float* __restrict__ w,
                                                 float* __restrict__ out) {
    constexpr int HOUT = HIN * 2;
    __shared__ float ws[COB * CISTEP * 9];

    const int n   = blockIdx.y;
    const int cob = blockIdx.z * COB;
    const int tid = threadIdx.x;
    const int ty  = tid / TW;
    const int tx  = tid % TW;
    const int a   = blockIdx.x * TH + ty;
    const int b   = tx;

    const float* inB = in + (size_t)n * CIN * HIN * HIN;

    float acc[COB][4];
#pragma unroll
    for (int i = 0; i < COB; i++)
#pragma unroll
        for (int q = 0; q < 4; q++) acc[i][q] = 0.f;

    const bool bOK = (b + 1 < HIN);
    const bool aOK = (a + 1 < HIN);

    for (int ci0 = 0; ci0 < CIN; ci0 += CISTEP) {
        __syncthreads();
        for (int i = tid; i < COB * CISTEP * 9; i += TH * TW) {
            int co = i / (CISTEP * 9);
            int r  = i % (CISTEP * 9);
            int ci = r / 9;
            int k  = r % 9;
            ws[i] = w[(size_t)(cob + co) * CIN * 9 + (size_t)(ci0 + ci) * 9 + k];
        }
        __syncthreads();

#pragma unroll
        for (int ci = 0; ci < CISTEP; ci++) {
            const float* p = inB + (size_t)(ci0 + ci) * HIN * HIN + (size_t)a * HIN + b;
            float v00 = __ldg(p);
            float v01 = bOK ? __ldg(p + 1) : 0.f;
            float v10 = aOK ? __ldg(p + HIN) : 0.f;
            float v11 = (aOK && bOK) ? __ldg(p + HIN + 1) : 0.f;
#pragma unroll
            for (int co = 0; co < COB; co++) {
                const float* wr = &ws[(co * CISTEP + ci) * 9];
                acc[co][0] = fmaf(v00, wr[4], acc[co][0]);
                acc[co][1] = fmaf(v00, wr[3], fmaf(v01, wr[5], acc[co][1]));
                acc[co][2] = fmaf(v00, wr[1], fmaf(v10, wr[7], acc[co][2]));
                acc[co][3] = fmaf(v00, wr[0],
                             fmaf(v01, wr[2],
                             fmaf(v10, wr[6],
                             fmaf(v11, wr[8], acc[co][3]))));
            }
        }
    }

#pragma unroll
    for (int co = 0; co < COB; co++) {
        float r0, r1, r2, r3;
        if (ACT == 0) {
            r0 = fmaxf(acc[co][0], 0.f);
            r1 = fmaxf(acc[co][1], 0.f);
            r2 = fmaxf(acc[co][2], 0.f);
            r3 = fmaxf(acc[co][3], 0.f);
        } else {
            r0 = 1.f / (1.f + expf(-acc[co][0]));
            r1 = 1.f / (1.f + expf(-acc[co][1]));
            r2 = 1.f / (1.f + expf(-acc[co][2]));
            r3 = 1.f / (1.f + expf(-acc[co][3]));
        }
        float* o = out + ((size_t)n * COUT + cob + co) * HOUT * HOUT +
                   (size_t)(2 * a) * HOUT + 2 * b;
        *reinterpret_cast<float2*>(o)        = make_float2(r0, r1);
        *reinterpret_cast<float2*>(o + HOUT) = make_float2(r2, r3);
    }
}

// ---------------------------------------------------------------------------
// XLA GPU row-reduction emulation for 256 elements (FROZEN).
// ---------------------------------------------------------------------------
template <typename F>
__device__ __forceinline__ float xla_reduce256(F f) {
    float v[32];
#pragma unroll
    for (int l = 0; l < 32; l++) {
        float s = f(l);
#pragma unroll
        for (int i = 1; i < 8; i++) s = __fadd_rn(s, f(l + 32 * i));
        v[l] = s;
    }
    for (int off = 16; off; off >>= 1)
        for (int l = 0; l < off; l++) v[l] = __fadd_rn(v[l], v[l + off]);
    return v[0];
}

// ---------------------------------------------------------------------------
// Codebook prep (FROZEN arithmetic).
// ---------------------------------------------------------------------------
__global__ void cb_t_kernel(const float* __restrict__ cb) {
    int i = blockIdx.x * 256 + threadIdx.x;
    int d = i >> 10;
    int c = i & 1023;
    g_ct[i] = cb[(size_t)c * 256 + d];
}

__global__ void cb_norm_kernel(const float* __restrict__ cb) {
    int code = blockIdx.x * blockDim.x + threadIdx.x;   // 1024 threads
    if (code >= 1024) return;
    const float* r = cb + (size_t)code * 256;
    double sd = 0.0;
    for (int d = 0; d < 256; d++) {
        float v = r[d];
        sd = fma((double)v, (double)v, sd);
    }
    g_cnorm_d[code] = sd;
    g_cnorm_f[code] = xla_reduce256([&](int i) { return __fmul_rn(r[i], r[i]); });
}

__global__ void reset_flags_kernel() {
    if (threadIdx.x == 0) g_nflag = 0;
}

__device__ __forceinline__ void top2_merge(long long& b1, long long& b2,
                                           long long o1, long long o2) {
    if (o1 < b1) {
        b2 = (b1 < o2) ? b1 : o2;
        b1 = o1;
    } else {
        b2 = (b2 < o1) ? b2 : o1;
    }
}

// ---------------------------------------------------------------------------
// VQ phase A (FROZEN arithmetic).
// ---------------------------------------------------------------------------
__global__ void __launch_bounds__(128) vq_kernel(const float* __restrict__ z,
                                                 float* __restrict__ ids_f) {
    constexpr int V = 16;
    constexpr long long LLMAX = 0x7fffffffffffffffLL;
    __shared__ float zs[256 * V];
    __shared__ double invu_s[V];
    __shared__ int   bflag_s[V];
    __shared__ long long red1[4 * V];
    __shared__ long long red2[4 * V];

    const int tid = threadIdx.x;
    const int blk = blockIdx.x;          // 2048 blocks
    const int n   = blk >> 6;
    const int hw0 = (blk & 63) * V;
    const float* zb = z + (size_t)n * 256 * 1024 + hw0;

    for (int i = tid; i < V * 256; i += 128) {
        int v = i & 15;
        int d = i >> 4;
        zs[(d << 4) + v] = zb[(size_t)d * 1024 + v];
    }
    __syncthreads();

    if (tid < V) {
        float s = 0.f;
        for (int d = 0; d < 256; d++) {
            float zd = zs[(d << 4) + tid];
            s = __fadd_rn(s, __fmul_rn(zd, zd));
        }
        int e;
        frexpf(s, &e);              // s in [2^(e-1), 2^e), u = 2^(e-24)
        invu_s[tid] = ldexp(1.0, 24 - e);
        float lo = ldexpf(1.0f, e - 1);
        float hi = ldexpf(1.0f, e);
        bflag_s[tid] = ((s - lo) < 0.006f * s) || ((hi - s) < 3e-5f * hi);
    }
    __syncthreads();

    float acc[V][8];
#pragma unroll
    for (int v = 0; v < V; v++)
#pragma unroll
        for (int j = 0; j < 8; j++) acc[v][j] = 0.f;

    const float4* ctp = reinterpret_cast<const float4*>(g_ct) + tid * 2;
#pragma unroll 2
    for (int d = 0; d < 256; d++) {
        float4 c0 = __ldg(ctp + (size_t)d * 256);
        float4 c1 = __ldg(ctp + (size_t)d * 256 + 1);
        float cv[8] = {c0.x, c0.y, c0.z, c0.w, c1.x, c1.y, c1.z, c1.w};
#pragma unroll
        for (int v = 0; v < V; v++) {
            float zd = zs[(d << 4) + v];
#pragma unroll
            for (int j = 0; j < 8; j++) acc[v][j] = fmaf(zd, cv[j], acc[v][j]);
        }
    }

    double cnd[8];
#pragma unroll
    for (int j = 0; j < 8; j++) cnd[j] = g_cnorm_d[tid * 8 + j];

    const int lane = tid & 31;
    const int warp = tid >> 5;

#pragma unroll
    for (int v = 0; v < V; v++) {
        double invu = invu_s[v];
        long long b1 = LLMAX, b2 = LLMAX;
#pragma unroll
        for (int j = 0; j < 8; j++) {
            double p = 2.0 * (double)acc[v][j];
            long long key = llrint(cnd[j] * invu) - llrint(p * invu);
            long long pk = (key << 10) | (long long)(tid * 8 + j);
            if (pk < b1) { b2 = b1; b1 = pk; }
            else if (pk < b2) { b2 = pk; }
        }
#pragma unroll
        for (int off = 16; off; off >>= 1) {
            long long o1 = __shfl_xor_sync(0xffffffffu, b1, off);
            long long o2 = __shfl_xor_sync(0xffffffffu, b2, off);
            top2_merge(b1, b2, o1, o2);
        }
        if (lane == 0) { red1[warp * V + v] = b1; red2[warp * V + v] = b2; }
    }
    __syncthreads();

    if (tid < V) {
        long long b1 = red1[tid], b2 = red2[tid];
#pragma unroll
        for (int w = 1; w < 4; w++) top2_merge(b1, b2, red1[w * V + tid], red2[w * V + tid]);
        int id  = (int)(b1 & 1023);
        int row = n * 1024 + hw0 + tid;
        g_ids[row] = id;
        ids_f[row] = (float)id;
        long long margin = (b2 >> 10) - (b1 >> 10);
        if (margin <= 24 || bflag_s[tid]) {
            int slot = atomicAdd(&g_nflag, 1);
            if (slot < 16384) g_flagrows[slot] = row;
        }
    }
}

// ---------------------------------------------------------------------------
// VQ phase B (FROZEN arithmetic).
// ---------------------------------------------------------------------------
__global__ void __launch_bounds__(256) vq_fix_kernel(const float* __restrict__ z,
                                                     float* __restrict__ ids_f) {
    int nf = g_nflag;
    if (nf > 16384) nf = 16384;
    if ((int)blockIdx.x >= nf) return;
    const int row = g_flagrows[blockIdx.x];
    const int n = row >> 10;
    const int hw = row & 1023;
    const int t = threadIdx.x;

    __shared__ float zsh[256];
    __shared__ float znf_sh;
    __shared__ unsigned long long redp[8];

    zsh[t] = z[((size_t)n * 256 + t) * 1024 + hw];
    __syncthreads();

    if (t == 0) {
        znf_sh = xla_reduce256([&](int i) { return __fmul_rn(zsh[i], zsh[i]); });
    }
    __syncthreads();
    const float znf = znf_sh;

    unsigned long long best = 0xffffffffffffffffULL;
#pragma unroll
    for (int q = 0; q < 4; q++) {
        int j = t + 256 * q;
        float a = 0.f;
        for (int d = 0; d < 256; d++)
            a = fmaf(2.0f * zsh[d], g_ct[d * 1024 + j], a);   // seq ascending-k
        float s1 = __fadd_rn(znf, -a);                        // fl(znorm - 2m)
        float dj = __fadd_rn(s1, g_cnorm_f[j]);               // fl(... + cn)
        unsigned bb  = __float_as_uint(dj);
        unsigned key = (bb & 0x80000000u) ? ~bb : (bb | 0x80000000u);
        unsigned long long pk = ((unsigned long long)key << 32) | (unsigned)j;
        if (pk < best) best = pk;
    }
#pragma unroll
    for (int off = 16; off; off >>= 1) {
        unsigned long long o = __shfl_xor_sync(0xffffffffu, best, off);
        if (o < best) best = o;
    }
    if ((t & 31) == 0) redp[t >> 5] = best;
    __syncthreads();
    if (t == 0) {
        unsigned long long b = redp[0];
#pragma unroll
        for (int w = 1; w < 8; w++) if (redp[w] < b) b = redp[w];
        int id = (int)(b & 0xffffffffu);
        g_ids[row] = id;
        ids_f[row] = (float)id;
    }
}

// e_k[n][c][hw] = codebook[ids[n][hw]][c]
__global__ void ek_kernel(const float* __restrict__ cb, float* __restrict__ ek) {
    size_t i = (size_t)blockIdx.x * 256 + threadIdx.x;
    int hw = (int)(i & 1023);
    int c  = (int)((i >> 10) & 255);
    int n  = (int)(i >> 18);
    int id = g_ids[n * 1024 + hw];
    ek[i] = cb[(size_t)id * 256 + c];
}

// ---------------------------------------------------------------------------
extern "C" void kernel_launch(void* const* d_in, const int* in_sizes, int n_in,
                              void* d_out, int out_size) {
    const float* x   = (const float*)d_in[0];
    const float* ew0 = (const float*)d_in[1];
    const float* ew1 = (const float*)d_in[2];
    const float* ew2 = (const float*)d_in[3];
    const float* cb  = (const float*)d_in[4];
    const float* dw0 = (const float*)d_in[5];
    const float* dw1 = (const float*)d_in[6];
    const float* dw2 = (const float*)d_in[7];
    float* out = (float*)d_out;

    float* bufA = nullptr;
    float* bufB = nullptr;
    cudaGetSymbolAddress((void**)&bufA, g_bufA);
    cudaGetSymbolAddress((void**)&bufB, g_bufB);

    // encoder (single-accumulator (kh,kw,ci) order — bit-frozen)
    conv_s2<3, 64, 256, 16, 1, 128, true><<<dim3(128, 32, 4), 128>>>(x, ew0, bufA);
    conv_s2<64, 128, 128, 16, 2, 64, true><<<dim3(32, 32, 8), 128>>>(bufA, ew1, bufB);
    conv_s2<128, 256, 64, 8, 4, 32, false><<<dim3(8, 32, 32), 128>>>(bufB, ew2, out + Z_OFF);

    // VQ
    cb_t_kernel<<<1024, 256>>>(cb);
    cb_norm_kernel<<<4, 256>>>(cb);
    reset_flags_kernel<<<1, 32>>>();
    vq_kernel<<<2048, 128>>>(out + Z_OFF, out + IDS_OFF);
    vq_fix_kernel<<<16384, 256>>>(out + Z_OFF, out + IDS_OFF);
    ek_kernel<<<32768, 256>>>(cb, out + EK_OFF);

    // decoder (precision-free; vectorized, COB=16)
    deconv_s2_v<256, 128, 32, 16, 4, 32, 8, 0><<<dim3(8, 32, 8), 128>>>(out + EK_OFF, dw0, bufB);
    deconv_s2_v<128, 64, 64, 16, 2, 64, 8, 0><<<dim3(32, 32, 4), 128>>>(bufB, dw1, bufA);
    deconv_s2<64, 3, 128, 3, 1, 128, 8, 1><<<dim3(128, 32, 1), 128>>>(bufA, dw2, out + OUT_OFF);
}

// round 15
// speedup vs baseline: 1.5412x; 1.5412x over previous
#include <cuda_runtime.h>
#include <math.h>
#include <stdint.h>

// ---------------------------------------------------------------------------
// VQ-VAE forward, fp32 direct kernels.
// Output layout (concatenated, float32): out | z | e_k | ids
// ENCODER + VQ ARITHMETIC IS FROZEN (bit-load-bearing for ids). Per-output
// accumulation order must stay: single accumulator, (kh,kw,ci) ascending,
// oob taps skipped. Only data movement / work mapping may change.
// ---------------------------------------------------------------------------

static const size_t OUT_OFF = 0;
static const size_t Z_OFF   = (size_t)32 * 3 * 256 * 256;
static const size_t EK_OFF  = Z_OFF + (size_t)32 * 256 * 32 * 32;
static const size_t IDS_OFF = EK_OFF + (size_t)32 * 256 * 32 * 32;

__device__ __align__(16) float g_bufA[(size_t)32 * 64 * 128 * 128];
__device__ __align__(16) float g_bufB[(size_t)32 * 128 * 64 * 64];
__device__ __align__(16) float g_ct[256 * 1024];     // codebook^T [d][code]
__device__ __align__(16) double g_cnorm_d[1024];     // exact norms (phase A keys)
__device__ __align__(16) float g_cnorm_f[1024];      // XLA-warp-order fp32 norms
__device__ int g_ids[32 * 1024];
__device__ int g_nflag;
__device__ int g_flagrows[16384];

#define POS_INF_F __int_as_float(0x7f800000)

// ---------------------------------------------------------------------------
// Conv2d k=3 s=2 p=1 (R12 scalar form) — used for conv1 (CIN=3).
// ---------------------------------------------------------------------------
template <int CIN, int COUT, int HIN, int COB, int TH, int TW, bool RELU>
__global__ void __launch_bounds__(128) conv_s2(const float* __restrict__ in,
                                               const float* __restrict__ w,
                                               float* __restrict__ out) {
    constexpr int HOUT = HIN / 2;
    constexpr int WOUT = HIN / 2;
    __shared__ float ws[COB * CIN * 9];

    const int n   = blockIdx.y;
    const int cob = blockIdx.z * COB;
    const int tid = threadIdx.x;
    const int ty  = tid / TW;
    const int tx  = tid % TW;
    const int oh  = blockIdx.x * TH + ty;
    const int ow  = tx;

    const float* inB = in + (size_t)n * CIN * HIN * HIN;

    for (int i = tid; i < COB * CIN * 9; i += TH * TW)
        ws[i] = w[(size_t)(cob + i / (CIN * 9)) * CIN * 9 + (i % (CIN * 9))];
    __syncthreads();

    float acc[COB];
#pragma unroll
    for (int i = 0; i < COB; i++) acc[i] = 0.f;

#pragma unroll
    for (int kh = 0; kh < 3; kh++) {
        int ih = 2 * oh - 1 + kh;
        if ((unsigned)ih >= (unsigned)HIN) continue;
#pragma unroll
        for (int kw = 0; kw < 3; kw++) {
            int iw = 2 * ow - 1 + kw;
            if ((unsigned)iw >= (unsigned)HIN) continue;
            const int k = kh * 3 + kw;
            const float* bp = inB + (size_t)ih * HIN + iw;
#pragma unroll 4
            for (int ci = 0; ci < CIN; ci++) {
                float xv = __ldg(bp + (size_t)ci * HIN * HIN);
#pragma unroll
                for (int co = 0; co < COB; co++)
                    acc[co] = fmaf(xv, ws[(co * CIN + ci) * 9 + k], acc[co]);
            }
        }
    }

    float* o = out + ((size_t)n * COUT + cob) * HOUT * WOUT + (size_t)oh * WOUT + ow;
#pragma unroll
    for (int co = 0; co < COB; co++) {
        float v = acc[co];
        if (RELU) v = fmaxf(v, 0.f);
        o[(size_t)co * HOUT * WOUT] = v;
    }
}

// ---------------------------------------------------------------------------
// Conv2d k=3 s=2 p=1, 2 output pixels per thread (ow0=tx, ow1=tx+TW).
// Requires WOUT == 2*TW. Weight reads amortized over 2 outputs.
// Per-output accumulation order identical to conv_s2 (FROZEN).
// Note: ow1 taps are always in-bounds (iw1 in [2TW-1, HIN-1]); ow0's only
// oob tap is (tx==0, kw==0), handled by the peeled else-branch (exact skip).
// ---------------------------------------------------------------------------
template <int CIN, int COUT, int HIN, int COB, int TH, int TW, bool RELU>
__global__ void __launch_bounds__(128) conv_s2_p2(const float* __restrict__ in,
                                                  const float* __restrict__ w,
                                                  float* __restrict__ out) {
    constexpr int HOUT = HIN / 2;
    constexpr int WOUT = HIN / 2;
    static_assert(WOUT == 2 * TW, "WOUT must equal 2*TW");
    static_assert(TH * TW == 128, "block must be 128 threads");
    __shared__ float ws[COB * CIN * 9];

    const int n   = blockIdx.y;
    const int cob = blockIdx.z * COB;
    const int tid = threadIdx.x;
    const int ty  = tid / TW;
    const int tx  = tid % TW;
    const int oh  = blockIdx.x * TH + ty;

    const float* inB = in + (size_t)n * CIN * HIN * HIN;
    constexpr size_t HH = (size_t)HIN * HIN;

    for (int i = tid; i < COB * CIN * 9; i += TH * TW)
        ws[i] = w[(size_t)(cob + i / (CIN * 9)) * CIN * 9 + (i % (CIN * 9))];
    __syncthreads();

    float acc0[COB], acc1[COB];
#pragma unroll
    for (int i = 0; i < COB; i++) { acc0[i] = 0.f; acc1[i] = 0.f; }

#pragma unroll
    for (int kh = 0; kh < 3; kh++) {
        int ih = 2 * oh - 1 + kh;
        if ((unsigned)ih >= (unsigned)HIN) continue;
#pragma unroll
        for (int kw = 0; kw < 3; kw++) {
            const int k = kh * 3 + kw;
            int iw0 = 2 * tx - 1 + kw;
            int iw1 = 2 * (tx + TW) - 1 + kw;   // always in [0, HIN)
            const float* bp = inB + (size_t)ih * HIN;
            if (iw0 >= 0) {
#pragma unroll 4
                for (int ci = 0; ci < CIN; ci++) {
                    float xv0 = __ldg(bp + ci * HH + iw0);
                    float xv1 = __ldg(bp + ci * HH + iw1);
#pragma unroll
                    for (int co = 0; co < COB; co++) {
                        float wv = ws[(co * CIN + ci) * 9 + k];
                        acc0[co] = fmaf(xv0, wv, acc0[co]);
                        acc1[co] = fmaf(xv1, wv, acc1[co]);
                    }
                }
            } else {
                // tx==0 && kw==0: pixel0 tap skipped (exact), pixel1 proceeds
#pragma unroll 4
                for (int ci = 0; ci < CIN; ci++) {
                    float xv1 = __ldg(bp + ci * HH + iw1);
#pragma unroll
                    for (int co = 0; co < COB; co++) {
                        float wv = ws[(co * CIN + ci) * 9 + k];
                        acc1[co] = fmaf(xv1, wv, acc1[co]);
                    }
                }
            }
        }
    }

    float* o = out + ((size_t)n * COUT + cob) * HOUT * WOUT + (size_t)oh * WOUT;
#pragma unroll
    for (int co = 0; co < COB; co++) {
        float v0 = acc0[co], v1 = acc1[co];
        if (RELU) { v0 = fmaxf(v0, 0.f); v1 = fmaxf(v1, 0.f); }
        o[(size_t)co * HOUT * WOUT + tx]      = v0;
        o[(size_t)co * HOUT * WOUT + tx + TW] = v1;
    }
}

// ---------------------------------------------------------------------------
// ConvTranspose2d k=3 s=2 p=1 outpad=1, 2 input pixels (b0=tx, b1=tx+TW) per
// thread; requires HIN == 2*TW. ACT: 0 = relu, 1 = sigmoid. Decoder precision
// does not affect ids.
// ---------------------------------------------------------------------------
template <int CIN, int COUT, int HIN, int COB, int TH, int TW, int CISTEP, int ACT>
__global__ void __launch_bounds__(128) deconv_s2_p2(const float* __restrict__ in,
                                                    const float* __restrict__ w,
                                                    float* __restrict__ out) {
    constexpr int HOUT = HIN * 2;
    static_assert(HIN == 2 * TW, "HIN must equal 2*TW");
    static_assert(TH * TW == 128, "block must be 128 threads");
    __shared__ float ws[COB * CISTEP * 9];

    const int n   = blockIdx.y;
    const int cob = blockIdx.z * COB;
    const int tid = threadIdx.x;
    const int ty  = tid / TW;
    const int tx  = tid % TW;
    const int a   = blockIdx.x * TH + ty;
    const int b0  = tx;
    const int b1  = tx + TW;

    const float* inB = in + (size_t)n * CIN * HIN * HIN;
    constexpr size_t HH = (size_t)HIN * HIN;

    float acc[2][COB][4];
#pragma unroll
    for (int p = 0; p < 2; p++)
#pragma unroll
        for (int i = 0; i < COB; i++)
#pragma unroll
            for (int q = 0; q < 4; q++) acc[p][i][q] = 0.f;

    const bool aOK  = (a + 1 < HIN);
    const bool bOK1 = (b1 + 1 < HIN);   // b0+1 < HIN always

    for (int ci0 = 0; ci0 < CIN; ci0 += CISTEP) {
        __syncthreads();
        for (int i = tid; i < COB * CISTEP * 9; i += TH * TW) {
            int co = i / (CISTEP * 9);
            int r  = i % (CISTEP * 9);
            int ci = r / 9;
            int k  = r % 9;
            ws[i] = w[(size_t)(cob + co) * CIN * 9 + (size_t)(ci0 + ci) * 9 + k];
        }
        __syncthreads();

#pragma unroll
        for (int ci = 0; ci < CISTEP; ci++) {
            const float* p0 = inB + (size_t)(ci0 + ci) * HH + (size_t)a * HIN + b0;
            const float* p1 = p0 + TW;
            float a00 = __ldg(p0);
            float a01 = __ldg(p0 + 1);
            float a10 = aOK ? __ldg(p0 + HIN) : 0.f;
            float a11 = aOK ? __ldg(p0 + HIN + 1) : 0.f;
            float c00 = __ldg(p1);
            float c01 = bOK1 ? __ldg(p1 + 1) : 0.f;
            float c10 = aOK ? __ldg(p1 + HIN) : 0.f;
            float c11 = (aOK && bOK1) ? __ldg(p1 + HIN + 1) : 0.f;
#pragma unroll
            for (int co = 0; co < COB; co++) {
                const float* wr = &ws[(co * CISTEP + ci) * 9];
                float w0 = wr[0], w1 = wr[1], w2 = wr[2], w3 = wr[3], w4 = wr[4];
                float w5 = wr[5], w6 = wr[6], w7 = wr[7], w8 = wr[8];
                acc[0][co][0] = fmaf(a00, w4, acc[0][co][0]);
                acc[0][co][1] = fmaf(a00, w3, fmaf(a01, w5, acc[0][co][1]));
                acc[0][co][2] = fmaf(a00, w1, fmaf(a10, w7, acc[0][co][2]));
                acc[0][co][3] = fmaf(a00, w0, fmaf(a01, w2,
                                fmaf(a10, w6, fmaf(a11, w8, acc[0][co][3]))));
                acc[1][co][0] = fmaf(c00, w4, acc[1][co][0]);
                acc[1][co][1] = fmaf(c00, w3, fmaf(c01, w5, acc[1][co][1]));
                acc[1][co][2] = fmaf(c00, w1, fmaf(c10, w7, acc[1][co][2]));
                acc[1][co][3] = fmaf(c00, w0, fmaf(c01, w2,
                                fmaf(c10, w6, fmaf(c11, w8, acc[1][co][3]))));
            }
        }
    }

#pragma unroll
    for (int p = 0; p < 2; p++) {
        int b = (p == 0) ? b0 : b1;
#pragma unroll
        for (int co = 0; co < COB; co++) {
            float r0, r1, r2, r3;
            if (ACT == 0) {
                r0 = fmaxf(acc[p][co][0], 0.f);
                r1 = fmaxf(acc[p][co][1], 0.f);
                r2 = fmaxf(acc[p][co][2], 0.f);
                r3 = fmaxf(acc[p][co][3], 0.f);
            } else {
                r0 = 1.f / (1.f + expf(-acc[p][co][0]));
                r1 = 1.f / (1.f + expf(-acc[p][co][1]));
                r2 = 1.f / (1.f + expf(-acc[p][co][2]));
                r3 = 1.f / (1.f + expf(-acc[p][co][3]));
            }
            float* o = out + ((size_t)n * COUT + cob + co) * HOUT * HOUT +
                       (size_t)(2 * a) * HOUT + 2 * b;
            *reinterpret_cast<float2*>(o)        = make_float2(r0, r1);
            *reinterpret_cast<float2*>(o + HOUT) = make_float2(r2, r3);
        }
    }
}

// Scalar deconv (for COUT=3 final layer).
template <int CIN, int COUT, int HIN, int COB, int TH, int TW, int CISTEP, int ACT>
__global__ void __launch_bounds__(128) deconv_s2(const float* __restrict__ in,
                                                 const float* __restrict__ w,
                                                 float* __restrict__ out) {
    constexpr int HOUT = HIN * 2;
    __shared__ float ws[COB * CISTEP * 9];

    const int n   = blockIdx.y;
    const int cob = blockIdx.z * COB;
    const int tid = threadIdx.x;
    const int ty  = tid / TW;
    const int tx  = tid % TW;
    const int a   = blockIdx.x * TH + ty;
    const int b   = tx;

    const float* inB = in + (size_t)n * CIN * HIN * HIN;

    float acc[COB][4];
#pragma unroll
    for (int i = 0; i < COB; i++)
#pragma unroll
        for (int q = 0; q < 4; q++) acc[i][q] = 0.f;

    const bool bOK = (b + 1 < HIN);
    const bool aOK = (a + 1 < HIN);

    for (int ci0 = 0; ci0 < CIN; ci0 += CISTEP) {
        __syncthreads();
        for (int i = tid; i < COB * CISTEP * 9; i += TH * TW) {
            int co = i / (CISTEP * 9);
            int r  = i % (CISTEP * 9);
            int ci = r / 9;
            int k  = r % 9;
            ws[i] = w[(size_t)(cob + co) * CIN * 9 + (size_t)(ci0 + ci) * 9 + k];
        }
        __syncthreads();

#pragma unroll
        for (int ci = 0; ci < CISTEP; ci++) {
            const float* p = inB + (size_t)(ci0 + ci) * HIN * HIN + (size_t)a * HIN + b;
            float v00 = __ldg(p);
            float v01 = bOK ? __ldg(p + 1) : 0.f;
            float v10 = aOK ? __ldg(p + HIN) : 0.f;
            float v11 = (aOK && bOK) ? __ldg(p + HIN + 1) : 0.f;
#pragma unroll
            for (int co = 0; co < COB; co++) {
                const float* wr = &ws[(co * CISTEP + ci) * 9];
                acc[co][0] = fmaf(v00, wr[4], acc[co][0]);
                acc[co][1] = fmaf(v00, wr[3], fmaf(v01, wr[5], acc[co][1]));
                acc[co][2] = fmaf(v00, wr[1], fmaf(v10, wr[7], acc[co][2]));
                acc[co][3] = fmaf(v00, wr[0],
                             fmaf(v01, wr[2],
                             fmaf(v10, wr[6],
                             fmaf(v11, wr[8], acc[co][3]))));
            }
        }
    }

#pragma unroll
    for (int co = 0; co < COB; co++) {
        float r0, r1, r2, r3;
        if (ACT == 0) {
            r0 = fmaxf(acc[co][0], 0.f);
            r1 = fmaxf(acc[co][1], 0.f);
            r2 = fmaxf(acc[co][2], 0.f);
            r3 = fmaxf(acc[co][3], 0.f);
        } else {
            r0 = 1.f / (1.f + expf(-acc[co][0]));
            r1 = 1.f / (1.f + expf(-acc[co][1]));
            r2 = 1.f / (1.f + expf(-acc[co][2]));
            r3 = 1.f / (1.f + expf(-acc[co][3]));
        }
        float* o = out + ((size_t)n * COUT + cob + co) * HOUT * HOUT +
                   (size_t)(2 * a) * HOUT + 2 * b;
        *reinterpret_cast<float2*>(o)        = make_float2(r0, r1);
        *reinterpret_cast<float2*>(o + HOUT) = make_float2(r2, r3);
    }
}

// ---------------------------------------------------------------------------
// XLA GPU row-reduction emulation for 256 elements (FROZEN).
// ---------------------------------------------------------------------------
template <typename F>
__device__ __forceinline__ float xla_reduce256(F f) {
    float v[32];
#pragma unroll
    for (int l = 0; l < 32; l++) {
        float s = f(l);
#pragma unroll
        for (int i = 1; i < 8; i++) s = __fadd_rn(s, f(l + 32 * i));
        v[l] = s;
    }
    for (int off = 16; off; off >>= 1)
        for (int l = 0; l < off; l++) v[l] = __fadd_rn(v[l], v[l + off]);
    return v[0];
}

// ---------------------------------------------------------------------------
// Codebook prep (FROZEN arithmetic).
// ---------------------------------------------------------------------------
__global__ void cb_t_kernel(const float* __restrict__ cb) {
    int i = blockIdx.x * 256 + threadIdx.x;
    int d = i >> 10;
    int c = i & 1023;
    g_ct[i] = cb[(size_t)c * 256 + d];
}

__global__ void cb_norm_kernel(const float* __restrict__ cb) {
    int code = blockIdx.x * blockDim.x + threadIdx.x;   // 1024 threads
    if (code >= 1024) return;
    const float* r = cb + (size_t)code * 256;
    double sd = 0.0;
    for (int d = 0; d < 256; d++) {
        float v = r[d];
        sd = fma((double)v, (double)v, sd);
    }
    g_cnorm_d[code] = sd;
    g_cnorm_f[code] = xla_reduce256([&](int i) { return __fmul_rn(r[i], r[i]); });
}

__global__ void reset_flags_kernel() {
    if (threadIdx.x == 0) g_nflag = 0;
}

__device__ __forceinline__ void top2_merge(long long& b1, long long& b2,
                                           long long o1, long long o2) {
    if (o1 < b1) {
        b2 = (b1 < o2) ? b1 : o2;
        b1 = o1;
    } else {
        b2 = (b2 < o1) ? b2 : o1;
    }
}

// ---------------------------------------------------------------------------
// VQ phase A (FROZEN arithmetic).
// ---------------------------------------------------------------------------
__global__ void __launch_bounds__(128) vq_kernel(const float* __restrict__ z,
                                                 float* __restrict__ ids_f) {
    constexpr int V = 16;
    constexpr long long LLMAX = 0x7fffffffffffffffLL;
    __shared__ float zs[256 * V];
    __shared__ double invu_s[V];
    __shared__ int   bflag_s[V];
    __shared__ long long red1[4 * V];
    __shared__ long long red2[4 * V];

    const int tid = threadIdx.x;
    const int blk = blockIdx.x;          // 2048 blocks
    const int n   = blk >> 6;
    const int hw0 = (blk & 63) * V;
    const float* zb = z + (size_t)n * 256 * 1024 + hw0;

    for (int i = tid; i < V * 256; i += 128) {
        int v = i & 15;
        int d = i >> 4;
        zs[(d << 4) + v] = zb[(size_t)d * 1024 + v];
    }
    __syncthreads();

    if (tid < V) {
        float s = 0.f;
        for (int d = 0; d < 256; d++) {
            float zd = zs[(d << 4) + tid];
            s = __fadd_rn(s, __fmul_rn(zd, zd));
        }
        int e;
        frexpf(s, &e);              // s in [2^(e-1), 2^e), u = 2^(e-24)
        invu_s[tid] = ldexp(1.0, 24 - e);
        float lo = ldexpf(1.0f, e - 1);
        float hi = ldexpf(1.0f, e);
        bflag_s[tid] = ((s - lo) < 0.006f * s) || ((hi - s) < 3e-5f * hi);
    }
    __syncthreads();

    float acc[V][8];
#pragma unroll
    for (int v = 0; v < V; v++)
#pragma unroll
        for (int j = 0; j < 8; j++) acc[v][j] = 0.f;

    const float4* ctp = reinterpret_cast<const float4*>(g_ct) + tid * 2;
#pragma unroll 2
    for (int d = 0; d < 256; d++) {
        float4 c0 = __ldg(ctp + (size_t)d * 256);
        float4 c1 = __ldg(ctp + (size_t)d * 256 + 1);
        float cv[8] = {c0.x, c0.y, c0.z, c0.w, c1.x, c1.y, c1.z, c1.w};
#pragma unroll
        for (int v = 0; v < V; v++) {
            float zd = zs[(d << 4) + v];
#pragma unroll
            for (int j = 0; j < 8; j++) acc[v][j] = fmaf(zd, cv[j], acc[v][j]);
        }
    }

    double cnd[8];
#pragma unroll
    for (int j = 0; j < 8; j++) cnd[j] = g_cnorm_d[tid * 8 + j];

    const int lane = tid & 31;
    const int warp = tid >> 5;

#pragma unroll
    for (int v = 0; v < V; v++) {
        double invu = invu_s[v];
        long long b1 = LLMAX, b2 = LLMAX;
#pragma unroll
        for (int j = 0; j < 8; j++) {
            double p = 2.0 * (double)acc[v][j];
            long long key = llrint(cnd[j] * invu) - llrint(p * invu);
            long long pk = (key << 10) | (long long)(tid * 8 + j);
            if (pk < b1) { b2 = b1; b1 = pk; }
            else if (pk < b2) { b2 = pk; }
        }
#pragma unroll
        for (int off = 16; off; off >>= 1) {
            long long o1 = __shfl_xor_sync(0xffffffffu, b1, off);
            long long o2 = __shfl_xor_sync(0xffffffffu, b2, off);
            top2_merge(b1, b2, o1, o2);
        }
        if (lane == 0) { red1[warp * V + v] = b1; red2[warp * V + v] = b2; }
    }
    __syncthreads();

    if (tid < V) {
        long long b1 = red1[tid], b2 = red2[tid];
#pragma unroll
        for (int w = 1; w < 4; w++) top2_merge(b1, b2, red1[w * V + tid], red2[w * V + tid]);
        int id  = (int)(b1 & 1023);
        int row = n * 1024 + hw0 + tid;
        g_ids[row] = id;
        ids_f[row] = (float)id;
        long long margin = (b2 >> 10) - (b1 >> 10);
        if (margin <= 24 || bflag_s[tid]) {
            int slot = atomicAdd(&g_nflag, 1);
            if (slot < 16384) g_flagrows[slot] = row;
        }
    }
}

// ---------------------------------------------------------------------------
// VQ phase B (FROZEN arithmetic).
// ---------------------------------------------------------------------------
__global__ void __launch_bounds__(256) vq_fix_kernel(const float* __restrict__ z,
                                                     float* __restrict__ ids_f) {
    int nf = g_nflag;
    if (nf > 16384) nf = 16384;
    if ((int)blockIdx.x >= nf) return;
    const int row = g_flagrows[blockIdx.x];
    const int n = row >> 10;
    const int hw = row & 1023;
    const int t = threadIdx.x;

    __shared__ float zsh[256];
    __shared__ float znf_sh;
    __shared__ unsigned long long redp[8];

    zsh[t] = z[((size_t)n * 256 + t) * 1024 + hw];
    __syncthreads();

    if (t == 0) {
        znf_sh = xla_reduce256([&](int i) { return __fmul_rn(zsh[i], zsh[i]); });
    }
    __syncthreads();
    const float znf = znf_sh;

    unsigned long long best = 0xffffffffffffffffULL;
#pragma unroll
    for (int q = 0; q < 4; q++) {
        int j = t + 256 * q;
        float a = 0.f;
        for (int d = 0; d < 256; d++)
            a = fmaf(2.0f * zsh[d], g_ct[d * 1024 + j], a);   // seq ascending-k
        float s1 = __fadd_rn(znf, -a);                        // fl(znorm - 2m)
        float dj = __fadd_rn(s1, g_cnorm_f[j]);               // fl(... + cn)
        unsigned bb  = __float_as_uint(dj);
        unsigned key = (bb & 0x80000000u) ? ~bb : (bb | 0x80000000u);
        unsigned long long pk = ((unsigned long long)key << 32) | (unsigned)j;
        if (pk < best) best = pk;
    }
#pragma unroll
    for (int off = 16; off; off >>= 1) {
        unsigned long long o = __shfl_xor_sync(0xffffffffu, best, off);
        if (o < best) best = o;
    }
    if ((t & 31) == 0) redp[t >> 5] = best;
    __syncthreads();
    if (t == 0) {
        unsigned long long b = redp[0];
#pragma unroll
        for (int w = 1; w < 8; w++) if (redp[w] < b) b = redp[w];
        int id = (int)(b & 0xffffffffu);
        g_ids[row] = id;
        ids_f[row] = (float)id;
    }
}

// e_k[n][c][hw] = codebook[ids[n][hw]][c]
__global__ void ek_kernel(const float* __restrict__ cb, float* __restrict__ ek) {
    size_t i = (size_t)blockIdx.x * 256 + threadIdx.x;
    int hw = (int)(i & 1023);
    int c  = (int)((i >> 10) & 255);
    int n  = (int)(i >> 18);
    int id = g_ids[n * 1024 + hw];
    ek[i] = cb[(size_t)id * 256 + c];
}

// ---------------------------------------------------------------------------
extern "C" void kernel_launch(void* const* d_in, const int* in_sizes, int n_in,
                              void* d_out, int out_size) {
    const float* x   = (const float*)d_in[0];
    const float* ew0 = (const float*)d_in[1];
    const float* ew1 = (const float*)d_in[2];
    const float* ew2 = (const float*)d_in[3];
    const float* cb  = (const float*)d_in[4];
    const float* dw0 = (const float*)d_in[5];
    const float* dw1 = (const float*)d_in[6];
    const float* dw2 = (const float*)d_in[7];
    float* out = (float*)d_out;

    float* bufA = nullptr;
    float* bufB = nullptr;
    cudaGetSymbolAddress((void**)&bufA, g_bufA);
    cudaGetSymbolAddress((void**)&bufB, g_bufB);

    // encoder (frozen per-output accumulation order)
    conv_s2<3, 64, 256, 16, 1, 128, true><<<dim3(128, 32, 4), 128>>>(x, ew0, bufA);
    conv_s2_p2<64, 128, 128, 16, 4, 32, true><<<dim3(16, 32, 8), 128>>>(bufA, ew1, bufB);
    conv_s2_p2<128, 256, 64, 8, 8, 16, false><<<dim3(4, 32, 32), 128>>>(bufB, ew2, out + Z_OFF);

    // VQ
    cb_t_kernel<<<1024, 256>>>(cb);
    cb_norm_kernel<<<4, 256>>>(cb);
    reset_flags_kernel<<<1, 32>>>();
    vq_kernel<<<2048, 128>>>(out + Z_OFF, out + IDS_OFF);
    vq_fix_kernel<<<16384, 256>>>(out + Z_OFF, out + IDS_OFF);
    ek_kernel<<<32768, 256>>>(cb, out + EK_OFF);

    // decoder
    deconv_s2_p2<256, 128, 32, 8, 8, 16, 8, 0><<<dim3(4, 32, 16), 128>>>(out + EK_OFF, dw0, bufB);
    deconv_s2_p2<128, 64, 64, 8, 4, 32, 8, 0><<<dim3(16, 32, 8), 128>>>(bufB, dw1, bufA);
    deconv_s2<64, 3, 128, 3, 1, 128, 8, 1><<<dim3(128, 32, 1), 128>>>(bufA, dw2, out + OUT_OFF);
}

// round 16
// speedup vs baseline: 1.8650x; 1.2101x over previous
#include <cuda_runtime.h>
#include <math.h>
#include <stdint.h>

// ---------------------------------------------------------------------------
// VQ-VAE forward, fp32 direct kernels.
// Output layout (concatenated, float32): out | z | e_k | ids
// ENCODER + VQ ARITHMETIC IS FROZEN (bit-load-bearing for ids). Per-output
// accumulation order must stay: single accumulator, (kh,kw,ci) ascending,
// oob taps skipped. Only data movement / work mapping may change.
// ---------------------------------------------------------------------------

static const size_t OUT_OFF = 0;
static const size_t Z_OFF   = (size_t)32 * 3 * 256 * 256;
static const size_t EK_OFF  = Z_OFF + (size_t)32 * 256 * 32 * 32;
static const size_t IDS_OFF = EK_OFF + (size_t)32 * 256 * 32 * 32;

__device__ __align__(16) float g_bufA[(size_t)32 * 64 * 128 * 128];
__device__ __align__(16) float g_bufB[(size_t)32 * 128 * 64 * 64];
__device__ __align__(16) float g_ct[256 * 1024];     // codebook^T [d][code]
__device__ __align__(16) double g_cnorm_d[1024];     // exact norms (phase A keys)
__device__ __align__(16) float g_cnorm_f[1024];      // XLA-warp-order fp32 norms
__device__ int g_ids[32 * 1024];
__device__ int g_nflag;
__device__ int g_flagrows[16384];

#define POS_INF_F __int_as_float(0x7f800000)

// ---------------------------------------------------------------------------
// Conv2d k=3 s=2 p=1, 2 output pixels per thread (ow0=tx, ow1=tx+TW),
// weights staged [k][ci][co] and read as float4 across co.
// Per-output accumulation chain (FROZEN): (kh,kw,ci) ascending, oob skipped.
// ow1 taps always in-bounds; ow0's only oob tap is (tx==0, kw==0) -> peeled.
// ---------------------------------------------------------------------------
template <int CIN, int COUT, int HIN, int COB, int TH, int TW, bool RELU>
__global__ void __launch_bounds__(128) conv_s2_p2v(const float* __restrict__ in,
                                                   const float* __restrict__ w,
                                                   float* __restrict__ out) {
    constexpr int HOUT = HIN / 2;
    constexpr int WOUT = HIN / 2;
    static_assert(WOUT == 2 * TW, "WOUT must equal 2*TW");
    static_assert(TH * TW == 128, "block must be 128 threads");
    static_assert(COB % 4 == 0, "COB multiple of 4");
    __shared__ __align__(16) float ws[9 * CIN * COB];   // [k][ci][co]

    const int n   = blockIdx.y;
    const int cob = blockIdx.z * COB;
    const int tid = threadIdx.x;
    const int ty  = tid / TW;
    const int tx  = tid % TW;
    const int oh  = blockIdx.x * TH + ty;

    const float* inB = in + (size_t)n * CIN * HIN * HIN;
    constexpr size_t HH = (size_t)HIN * HIN;

    // i is the linear [k][ci][co] index
    for (int i = tid; i < 9 * CIN * COB; i += 128) {
        int co = i % COB;
        int r  = i / COB;
        int ci = r % CIN;
        int k  = r / CIN;
        ws[i] = w[(size_t)(cob + co) * CIN * 9 + ci * 9 + k];
    }
    __syncthreads();

    float acc0[COB], acc1[COB];
#pragma unroll
    for (int i = 0; i < COB; i++) { acc0[i] = 0.f; acc1[i] = 0.f; }

#pragma unroll
    for (int kh = 0; kh < 3; kh++) {
        int ih = 2 * oh - 1 + kh;
        if ((unsigned)ih >= (unsigned)HIN) continue;
#pragma unroll
        for (int kw = 0; kw < 3; kw++) {
            const int k = kh * 3 + kw;
            int iw0 = 2 * tx - 1 + kw;
            int iw1 = 2 * (tx + TW) - 1 + kw;   // always in [0, HIN)
            const float* bp = inB + (size_t)ih * HIN;
            const float4* wk4 = reinterpret_cast<const float4*>(&ws[k * CIN * COB]);
            if (iw0 >= 0) {
#pragma unroll 4
                for (int ci = 0; ci < CIN; ci++) {
                    float xv0 = __ldg(bp + ci * HH + iw0);
                    float xv1 = __ldg(bp + ci * HH + iw1);
#pragma unroll
                    for (int c4 = 0; c4 < COB / 4; c4++) {
                        float4 wv = wk4[ci * (COB / 4) + c4];
                        acc0[c4 * 4 + 0] = fmaf(xv0, wv.x, acc0[c4 * 4 + 0]);
                        acc1[c4 * 4 + 0] = fmaf(xv1, wv.x, acc1[c4 * 4 + 0]);
                        acc0[c4 * 4 + 1] = fmaf(xv0, wv.y, acc0[c4 * 4 + 1]);
                        acc1[c4 * 4 + 1] = fmaf(xv1, wv.y, acc1[c4 * 4 + 1]);
                        acc0[c4 * 4 + 2] = fmaf(xv0, wv.z, acc0[c4 * 4 + 2]);
                        acc1[c4 * 4 + 2] = fmaf(xv1, wv.z, acc1[c4 * 4 + 2]);
                        acc0[c4 * 4 + 3] = fmaf(xv0, wv.w, acc0[c4 * 4 + 3]);
                        acc1[c4 * 4 + 3] = fmaf(xv1, wv.w, acc1[c4 * 4 + 3]);
                    }
                }
            } else {
                // tx==0 && kw==0: pixel0 tap skipped (exact), pixel1 proceeds
#pragma unroll 4
                for (int ci = 0; ci < CIN; ci++) {
                    float xv1 = __ldg(bp + ci * HH + iw1);
#pragma unroll
                    for (int c4 = 0; c4 < COB / 4; c4++) {
                        float4 wv = wk4[ci * (COB / 4) + c4];
                        acc1[c4 * 4 + 0] = fmaf(xv1, wv.x, acc1[c4 * 4 + 0]);
                        acc1[c4 * 4 + 1] = fmaf(xv1, wv.y, acc1[c4 * 4 + 1]);
                        acc1[c4 * 4 + 2] = fmaf(xv1, wv.z, acc1[c4 * 4 + 2]);
                        acc1[c4 * 4 + 3] = fmaf(xv1, wv.w, acc1[c4 * 4 + 3]);
                    }
                }
            }
        }
    }

    float* o = out + ((size_t)n * COUT + cob) * HOUT * WOUT + (size_t)oh * WOUT;
#pragma unroll
    for (int co = 0; co < COB; co++) {
        float v0 = acc0[co], v1 = acc1[co];
        if (RELU) { v0 = fmaxf(v0, 0.f); v1 = fmaxf(v1, 0.f); }
        o[(size_t)co * HOUT * WOUT + tx]      = v0;
        o[(size_t)co * HOUT * WOUT + tx + TW] = v1;
    }
}

// ---------------------------------------------------------------------------
// ConvTranspose2d k=3 s=2 p=1 outpad=1, 2 input pixels (b0=tx, b1=tx+TW) per
// thread; HIN == 2*TW. Weights padded to stride 12 -> 3x LDS.128 per (co,ci).
// ACT: 0 = relu, 1 = sigmoid. Decoder precision does not affect ids.
// ---------------------------------------------------------------------------
template <int CIN, int COUT, int HIN, int COB, int TH, int TW, int CISTEP, int ACT>
__global__ void __launch_bounds__(128) deconv_s2_p2(const float* __restrict__ in,
                                                    const float* __restrict__ w,
                                                    float* __restrict__ out) {
    constexpr int HOUT = HIN * 2;
    static_assert(HIN == 2 * TW, "HIN must equal 2*TW");
    static_assert(TH * TW == 128, "block must be 128 threads");
    __shared__ __align__(16) float ws[COB * CISTEP * 12];   // stride-12 padded

    const int n   = blockIdx.y;
    const int cob = blockIdx.z * COB;
    const int tid = threadIdx.x;
    const int ty  = tid / TW;
    const int tx  = tid % TW;
    const int a   = blockIdx.x * TH + ty;
    const int b0  = tx;
    const int b1  = tx + TW;

    const float* inB = in + (size_t)n * CIN * HIN * HIN;
    constexpr size_t HH = (size_t)HIN * HIN;

    float acc[2][COB][4];
#pragma unroll
    for (int p = 0; p < 2; p++)
#pragma unroll
        for (int i = 0; i < COB; i++)
#pragma unroll
            for (int q = 0; q < 4; q++) acc[p][i][q] = 0.f;

    const bool aOK  = (a + 1 < HIN);
    const bool bOK1 = (b1 + 1 < HIN);   // b0+1 < HIN always

    for (int ci0 = 0; ci0 < CIN; ci0 += CISTEP) {
        __syncthreads();
        for (int i = tid; i < COB * CISTEP * 9; i += 128) {
            int co = i / (CISTEP * 9);
            int r  = i % (CISTEP * 9);
            int ci = r / 9;
            int k  = r % 9;
            ws[(co * CISTEP + ci) * 12 + k] =
                w[(size_t)(cob + co) * CIN * 9 + (size_t)(ci0 + ci) * 9 + k];
        }
        __syncthreads();

#pragma unroll
        for (int ci = 0; ci < CISTEP; ci++) {
            const float* p0 = inB + (size_t)(ci0 + ci) * HH + (size_t)a * HIN + b0;
            const float* p1 = p0 + TW;
            float a00 = __ldg(p0);
            float a01 = __ldg(p0 + 1);
            float a10 = aOK ? __ldg(p0 + HIN) : 0.f;
            float a11 = aOK ? __ldg(p0 + HIN + 1) : 0.f;
            float c00 = __ldg(p1);
            float c01 = bOK1 ? __ldg(p1 + 1) : 0.f;
            float c10 = aOK ? __ldg(p1 + HIN) : 0.f;
            float c11 = (aOK && bOK1) ? __ldg(p1 + HIN + 1) : 0.f;
#pragma unroll
            for (int co = 0; co < COB; co++) {
                const float4* wp = reinterpret_cast<const float4*>(
                    &ws[(co * CISTEP + ci) * 12]);
                float4 wA = wp[0];   // w0 w1 w2 w3
                float4 wB = wp[1];   // w4 w5 w6 w7
                float4 wC = wp[2];   // w8 (pad pad pad)
                acc[0][co][0] = fmaf(a00, wB.x, acc[0][co][0]);
                acc[0][co][1] = fmaf(a00, wA.w, fmaf(a01, wB.y, acc[0][co][1]));
                acc[0][co][2] = fmaf(a00, wA.y, fmaf(a10, wB.w, acc[0][co][2]));
                acc[0][co][3] = fmaf(a00, wA.x, fmaf(a01, wA.z,
                                fmaf(a10, wB.z, fmaf(a11, wC.x, acc[0][co][3]))));
                acc[1][co][0] = fmaf(c00, wB.x, acc[1][co][0]);
                acc[1][co][1] = fmaf(c00, wA.w, fmaf(c01, wB.y, acc[1][co][1]));
                acc[1][co][2] = fmaf(c00, wA.y, fmaf(c10, wB.w, acc[1][co][2]));
                acc[1][co][3] = fmaf(c00, wA.x, fmaf(c01, wA.z,
                                fmaf(c10, wB.z, fmaf(c11, wC.x, acc[1][co][3]))));
            }
        }
    }

#pragma unroll
    for (int p = 0; p < 2; p++) {
        int b = (p == 0) ? b0 : b1;
#pragma unroll
        for (int co = 0; co < COB; co++) {
            float r0, r1, r2, r3;
            if (ACT == 0) {
                r0 = fmaxf(acc[p][co][0], 0.f);
                r1 = fmaxf(acc[p][co][1], 0.f);
                r2 = fmaxf(acc[p][co][2], 0.f);
                r3 = fmaxf(acc[p][co][3], 0.f);
            } else {
                r0 = 1.f / (1.f + expf(-acc[p][co][0]));
                r1 = 1.f / (1.f + expf(-acc[p][co][1]));
                r2 = 1.f / (1.f + expf(-acc[p][co][2]));
                r3 = 1.f / (1.f + expf(-acc[p][co][3]));
            }
            float* o = out + ((size_t)n * COUT + cob + co) * HOUT * HOUT +
                       (size_t)(2 * a) * HOUT + 2 * b;
            *reinterpret_cast<float2*>(o)        = make_float2(r0, r1);
            *reinterpret_cast<float2*>(o + HOUT) = make_float2(r2, r3);
        }
    }
}

// ---------------------------------------------------------------------------
// XLA GPU row-reduction emulation for 256 elements (FROZEN).
// ---------------------------------------------------------------------------
template <typename F>
__device__ __forceinline__ float xla_reduce256(F f) {
    float v[32];
#pragma unroll
    for (int l = 0; l < 32; l++) {
        float s = f(l);
#pragma unroll
        for (int i = 1; i < 8; i++) s = __fadd_rn(s, f(l + 32 * i));
        v[l] = s;
    }
    for (int off = 16; off; off >>= 1)
        for (int l = 0; l < off; l++) v[l] = __fadd_rn(v[l], v[l + off]);
    return v[0];
}

// ---------------------------------------------------------------------------
// Codebook prep (FROZEN arithmetic).
// ---------------------------------------------------------------------------
__global__ void cb_t_kernel(const float* __restrict__ cb) {
    int i = blockIdx.x * 256 + threadIdx.x;
    int d = i >> 10;
    int c = i & 1023;
    g_ct[i] = cb[(size_t)c * 256 + d];
}

__global__ void cb_norm_kernel(const float* __restrict__ cb) {
    int code = blockIdx.x * blockDim.x + threadIdx.x;   // 1024 threads
    if (code >= 1024) return;
    const float* r = cb + (size_t)code * 256;
    double sd = 0.0;
    for (int d = 0; d < 256; d++) {
        float v = r[d];
        sd = fma((double)v, (double)v, sd);
    }
    g_cnorm_d[code] = sd;
    g_cnorm_f[code] = xla_reduce256([&](int i) { return __fmul_rn(r[i], r[i]); });
}

__global__ void reset_flags_kernel() {
    if (threadIdx.x == 0) g_nflag = 0;
}

__device__ __forceinline__ void top2_merge(long long& b1, long long& b2,
                                           long long o1, long long o2) {
    if (o1 < b1) {
        b2 = (b1 < o2) ? b1 : o2;
        b1 = o1;
    } else {
        b2 = (b2 < o1) ? b2 : o1;
    }
}

// ---------------------------------------------------------------------------
// VQ phase A (FROZEN arithmetic).
// ---------------------------------------------------------------------------
__global__ void __launch_bounds__(128) vq_kernel(const float* __restrict__ z,
                                                 float* __restrict__ ids_f) {
    constexpr int V = 16;
    constexpr long long LLMAX = 0x7fffffffffffffffLL;
    __shared__ float zs[256 * V];
    __shared__ double invu_s[V];
    __shared__ int   bflag_s[V];
    __shared__ long long red1[4 * V];
    __shared__ long long red2[4 * V];

    const int tid = threadIdx.x;
    const int blk = blockIdx.x;          // 2048 blocks
    const int n   = blk >> 6;
    const int hw0 = (blk & 63) * V;
    const float* zb = z + (size_t)n * 256 * 1024 + hw0;

    for (int i = tid; i < V * 256; i += 128) {
        int v = i & 15;
        int d = i >> 4;
        zs[(d << 4) + v] = zb[(size_t)d * 1024 + v];
    }
    __syncthreads();

    if (tid < V) {
        float s = 0.f;
        for (int d = 0; d < 256; d++) {
            float zd = zs[(d << 4) + tid];
            s = __fadd_rn(s, __fmul_rn(zd, zd));
        }
        int e;
        frexpf(s, &e);              // s in [2^(e-1), 2^e), u = 2^(e-24)
        invu_s[tid] = ldexp(1.0, 24 - e);
        float lo = ldexpf(1.0f, e - 1);
        float hi = ldexpf(1.0f, e);
        bflag_s[tid] = ((s - lo) < 0.006f * s) || ((hi - s) < 3e-5f * hi);
    }
    __syncthreads();

    float acc[V][8];
#pragma unroll
    for (int v = 0; v < V; v++)
#pragma unroll
        for (int j = 0; j < 8; j++) acc[v][j] = 0.f;

    const float4* ctp = reinterpret_cast<const float4*>(g_ct) + tid * 2;
#pragma unroll 2
    for (int d = 0; d < 256; d++) {
        float4 c0 = __ldg(ctp + (size_t)d * 256);
        float4 c1 = __ldg(ctp + (size_t)d * 256 + 1);
        float cv[8] = {c0.x, c0.y, c0.z, c0.w, c1.x, c1.y, c1.z, c1.w};
#pragma unroll
        for (int v = 0; v < V; v++) {
            float zd = zs[(d << 4) + v];
#pragma unroll
            for (int j = 0; j < 8; j++) acc[v][j] = fmaf(zd, cv[j], acc[v][j]);
        }
    }

    double cnd[8];
#pragma unroll
    for (int j = 0; j < 8; j++) cnd[j] = g_cnorm_d[tid * 8 + j];

    const int lane = tid & 31;
    const int warp = tid >> 5;

#pragma unroll
    for (int v = 0; v < V; v++) {
        double invu = invu_s[v];
        long long b1 = LLMAX, b2 = LLMAX;
#pragma unroll
        for (int j = 0; j < 8; j++) {
            double p = 2.0 * (double)acc[v][j];
            long long key = llrint(cnd[j] * invu) - llrint(p * invu);
            long long pk = (key << 10) | (long long)(tid * 8 + j);
            if (pk < b1) { b2 = b1; b1 = pk; }
            else if (pk < b2) { b2 = pk; }
        }
#pragma unroll
        for (int off = 16; off; off >>= 1) {
            long long o1 = __shfl_xor_sync(0xffffffffu, b1, off);
            long long o2 = __shfl_xor_sync(0xffffffffu, b2, off);
            top2_merge(b1, b2, o1, o2);
        }
        if (lane == 0) { red1[warp * V + v] = b1; red2[warp * V + v] = b2; }
    }
    __syncthreads();

    if (tid < V) {
        long long b1 = red1[tid], b2 = red2[tid];
#pragma unroll
        for (int w = 1; w < 4; w++) top2_merge(b1, b2, red1[w * V + tid], red2[w * V + tid]);
        int id  = (int)(b1 & 1023);
        int row = n * 1024 + hw0 + tid;
        g_ids[row] = id;
        ids_f[row] = (float)id;
        long long margin = (b2 >> 10) - (b1 >> 10);
        if (margin <= 24 || bflag_s[tid]) {
            int slot = atomicAdd(&g_nflag, 1);
            if (slot < 16384) g_flagrows[slot] = row;
        }
    }
}

// ---------------------------------------------------------------------------
// VQ phase B (FROZEN arithmetic).
// ---------------------------------------------------------------------------
__global__ void __launch_bounds__(256) vq_fix_kernel(const float* __restrict__ z,
                                                     float* __restrict__ ids_f) {
    int nf = g_nflag;
    if (nf > 16384) nf = 16384;
    if ((int)blockIdx.x >= nf) return;
    const int row = g_flagrows[blockIdx.x];
    const int n = row >> 10;
    const int hw = row & 1023;
    const int t = threadIdx.x;

    __shared__ float zsh[256];
    __shared__ float znf_sh;
    __shared__ unsigned long long redp[8];

    zsh[t] = z[((size_t)n * 256 + t) * 1024 + hw];
    __syncthreads();

    if (t == 0) {
        znf_sh = xla_reduce256([&](int i) { return __fmul_rn(zsh[i], zsh[i]); });
    }
    __syncthreads();
    const float znf = znf_sh;

    unsigned long long best = 0xffffffffffffffffULL;
#pragma unroll
    for (int q = 0; q < 4; q++) {
        int j = t + 256 * q;
        float a = 0.f;
        for (int d = 0; d < 256; d++)
            a = fmaf(2.0f * zsh[d], g_ct[d * 1024 + j], a);   // seq ascending-k
        float s1 = __fadd_rn(znf, -a);                        // fl(znorm - 2m)
        float dj = __fadd_rn(s1, g_cnorm_f[j]);               // fl(... + cn)
        unsigned bb  = __float_as_uint(dj);
        unsigned key = (bb & 0x80000000u) ? ~bb : (bb | 0x80000000u);
        unsigned long long pk = ((unsigned long long)key << 32) | (unsigned)j;
        if (pk < best) best = pk;
    }
#pragma unroll
    for (int off = 16; off; off >>= 1) {
        unsigned long long o = __shfl_xor_sync(0xffffffffu, best, off);
        if (o < best) best = o;
    }
    if ((t & 31) == 0) redp[t >> 5] = best;
    __syncthreads();
    if (t == 0) {
        unsigned long long b = redp[0];
#pragma unroll
        for (int w = 1; w < 8; w++) if (redp[w] < b) b = redp[w];
        int id = (int)(b & 0xffffffffu);
        g_ids[row] = id;
        ids_f[row] = (float)id;
    }
}

// e_k[n][c][hw] = codebook[ids[n][hw]][c]
__global__ void ek_kernel(const float* __restrict__ cb, float* __restrict__ ek) {
    size_t i = (size_t)blockIdx.x * 256 + threadIdx.x;
    int hw = (int)(i & 1023);
    int c  = (int)((i >> 10) & 255);
    int n  = (int)(i >> 18);
    int id = g_ids[n * 1024 + hw];
    ek[i] = cb[(size_t)id * 256 + c];
}

// ---------------------------------------------------------------------------
extern "C" void kernel_launch(void* const* d_in, const int* in_sizes, int n_in,
                              void* d_out, int out_size) {
    const float* x   = (const float*)d_in[0];
    const float* ew0 = (const float*)d_in[1];
    const float* ew1 = (const float*)d_in[2];
    const float* ew2 = (const float*)d_in[3];
    const float* cb  = (const float*)d_in[4];
    const float* dw0 = (const float*)d_in[5];
    const float* dw1 = (const float*)d_in[6];
    const float* dw2 = (const float*)d_in[7];
    float* out = (float*)d_out;

    float* bufA = nullptr;
    float* bufB = nullptr;
    cudaGetSymbolAddress((void**)&bufA, g_bufA);
    cudaGetSymbolAddress((void**)&bufB, g_bufB);

    // encoder (frozen per-output accumulation order; vector weight loads)
    conv_s2_p2v<3, 64, 256, 16, 2, 64, true><<<dim3(64, 32, 4), 128>>>(x, ew0, bufA);
    conv_s2_p2v<64, 128, 128, 16, 4, 32, true><<<dim3(16, 32, 8), 128>>>(bufA, ew1, bufB);
    conv_s2_p2v<128, 256, 64, 8, 8, 16, false><<<dim3(4, 32, 32), 128>>>(bufB, ew2, out + Z_OFF);

    // VQ
    cb_t_kernel<<<1024, 256>>>(cb);
    cb_norm_kernel<<<4, 256>>>(cb);
    reset_flags_kernel<<<1, 32>>>();
    vq_kernel<<<2048, 128>>>(out + Z_OFF, out + IDS_OFF);
    vq_fix_kernel<<<16384, 256>>>(out + Z_OFF, out + IDS_OFF);
    ek_kernel<<<32768, 256>>>(cb, out + EK_OFF);

    // decoder (padded float4 weight loads)
    deconv_s2_p2<256, 128, 32, 8, 8, 16, 8, 0><<<dim3(4, 32, 16), 128>>>(out + EK_OFF, dw0, bufB);
    deconv_s2_p2<128, 64, 64, 8, 4, 32, 8, 0><<<dim3(16, 32, 8), 128>>>(bufB, dw1, bufA);
    deconv_s2_p2<64, 3, 128, 3, 2, 64, 8, 1><<<dim3(64, 32, 1), 128>>>(bufA, dw2, out + OUT_OFF);
}

// round 17
// speedup vs baseline: 2.1118x; 1.1323x over previous
#include <cuda_runtime.h>
#include <math.h>
#include <stdint.h>

// ---------------------------------------------------------------------------
// VQ-VAE forward, fp32 + packed f32x2 (FFMA2) kernels.
// Output layout (concatenated, float32): out | z | e_k | ids
// ENCODER + VQ ARITHMETIC IS FROZEN (bit-load-bearing for ids). FFMA2 halves
// are independent IEEE-RN fp32 FMAs, so pairing ACROSS output channels keeps
// every per-channel chain bit-identical: order stays (kh,kw,ci) ascending.
// ---------------------------------------------------------------------------

static const size_t OUT_OFF = 0;
static const size_t Z_OFF   = (size_t)32 * 3 * 256 * 256;
static const size_t EK_OFF  = Z_OFF + (size_t)32 * 256 * 32 * 32;
static const size_t IDS_OFF = EK_OFF + (size_t)32 * 256 * 32 * 32;

__device__ __align__(16) float g_bufA[(size_t)32 * 64 * 128 * 128];
__device__ __align__(16) float g_bufB[(size_t)32 * 128 * 64 * 64];
__device__ __align__(16) float g_ct[256 * 1024];     // codebook^T [d][code]
__device__ __align__(16) double g_cnorm_d[1024];     // exact norms (phase A keys)
__device__ __align__(16) float g_cnorm_f[1024];      // XLA-warp-order fp32 norms
__device__ int g_ids[32 * 1024];
__device__ int g_nflag;
__device__ int g_flagrows[16384];

#define POS_INF_F __int_as_float(0x7f800000)

// ---- packed f32x2 helpers --------------------------------------------------
typedef unsigned long long u64;

__device__ __forceinline__ u64 pack2(float lo, float hi) {
    u64 r;
    asm("mov.b64 %0, {%1, %2};" : "=l"(r) : "f"(lo), "f"(hi));
    return r;
}
__device__ __forceinline__ float2 unpack2(u64 v) {
    float2 r;
    asm("mov.b64 {%0, %1}, %2;" : "=f"(r.x), "=f"(r.y) : "l"(v));
    return r;
}
#define FFMA2(acc, x, w) \
    asm("fma.rn.f32x2 %0, %1, %2, %0;" : "+l"(acc) : "l"(x), "l"(w))

// ---------------------------------------------------------------------------
// Conv2d k=3 s=2 p=1, 2 output pixels per thread, co-paired FFMA2.
// Weights staged [k][ci][co]; LDS.128 across co gives 2 co-pairs free.
// Per-co accumulation chain (FROZEN): (kh,kw,ci) ascending; the boundary tap
// (tx==0,kw==0) uses xv0=0 which is bit-identical to skipping.
// ---------------------------------------------------------------------------
template <int CIN, int COUT, int HIN, int COB, int TH, int TW, bool RELU>
__global__ void __launch_bounds__(128) conv_s2_p2x(const float* __restrict__ in,
                                                   const float* __restrict__ w,
                                                   float* __restrict__ out) {
    constexpr int HOUT = HIN / 2;
    constexpr int WOUT = HIN / 2;
    static_assert(WOUT == 2 * TW, "WOUT must equal 2*TW");
    static_assert(TH * TW == 128, "block must be 128 threads");
    static_assert(COB % 4 == 0, "COB multiple of 4");
    __shared__ __align__(16) float ws[9 * CIN * COB];   // [k][ci][co]

    const int n   = blockIdx.y;
    const int cob = blockIdx.z * COB;
    const int tid = threadIdx.x;
    const int ty  = tid / TW;
    const int tx  = tid % TW;
    const int oh  = blockIdx.x * TH + ty;

    const float* inB = in + (size_t)n * CIN * HIN * HIN;
    constexpr size_t HH = (size_t)HIN * HIN;

    for (int i = tid; i < 9 * CIN * COB; i += 128) {
        int co = i % COB;
        int r  = i / COB;
        int ci = r % CIN;
        int k  = r / CIN;
        ws[i] = w[(size_t)(cob + co) * CIN * 9 + ci * 9 + k];
    }
    __syncthreads();

    // acc2[p][c2]: pixel p, co-pair c2 -> (co=2*c2, co=2*c2+1)
    u64 acc2[2][COB / 2];
#pragma unroll
    for (int p = 0; p < 2; p++)
#pragma unroll
        for (int i = 0; i < COB / 2; i++) acc2[p][i] = 0ull;

#pragma unroll
    for (int kh = 0; kh < 3; kh++) {
        int ih = 2 * oh - 1 + kh;
        if ((unsigned)ih >= (unsigned)HIN) continue;
#pragma unroll
        for (int kw = 0; kw < 3; kw++) {
            const int k = kh * 3 + kw;
            int iw0 = 2 * tx - 1 + kw;
            int iw1 = 2 * (tx + TW) - 1 + kw;   // always in [0, HIN)
            const float* bp = inB + (size_t)ih * HIN;
            const float4* wk4 = reinterpret_cast<const float4*>(&ws[k * CIN * COB]);
#pragma unroll 4
            for (int ci = 0; ci < CIN; ci++) {
                float xv0 = (iw0 >= 0) ? __ldg(bp + ci * HH + iw0) : 0.f;
                float xv1 = __ldg(bp + ci * HH + iw1);
                u64 x0d = pack2(xv0, xv0);
                u64 x1d = pack2(xv1, xv1);
#pragma unroll
                for (int c4 = 0; c4 < COB / 4; c4++) {
                    float4 wv = wk4[ci * (COB / 4) + c4];
                    u64 wp01 = pack2(wv.x, wv.y);
                    u64 wp23 = pack2(wv.z, wv.w);
                    FFMA2(acc2[0][c4 * 2],     x0d, wp01);
                    FFMA2(acc2[1][c4 * 2],     x1d, wp01);
                    FFMA2(acc2[0][c4 * 2 + 1], x0d, wp23);
                    FFMA2(acc2[1][c4 * 2 + 1], x1d, wp23);
                }
            }
        }
    }

    float* o = out + ((size_t)n * COUT + cob) * HOUT * WOUT + (size_t)oh * WOUT;
#pragma unroll
    for (int c2 = 0; c2 < COB / 2; c2++) {
        float2 v0 = unpack2(acc2[0][c2]);
        float2 v1 = unpack2(acc2[1][c2]);
        if (RELU) {
            v0.x = fmaxf(v0.x, 0.f); v0.y = fmaxf(v0.y, 0.f);
            v1.x = fmaxf(v1.x, 0.f); v1.y = fmaxf(v1.y, 0.f);
        }
        o[(size_t)(2 * c2)     * HOUT * WOUT + tx]      = v0.x;
        o[(size_t)(2 * c2 + 1) * HOUT * WOUT + tx]      = v0.y;
        o[(size_t)(2 * c2)     * HOUT * WOUT + tx + TW] = v1.x;
        o[(size_t)(2 * c2 + 1) * HOUT * WOUT + tx + TW] = v1.y;
    }
}

// ---------------------------------------------------------------------------
// ConvTranspose2d k=3 s=2 p=1 outpad=1, 2 input pixels per thread, co-paired
// FFMA2. Weights staged [ci][k][co]. ACT: 0 = relu, 1 = sigmoid.
// Decoder precision does not affect ids.
// ---------------------------------------------------------------------------
template <int CIN, int COUT, int HIN, int COB, int TH, int TW, int CISTEP, int ACT>
__global__ void __launch_bounds__(128) deconv_s2_p2x(const float* __restrict__ in,
                                                     const float* __restrict__ w,
                                                     float* __restrict__ out) {
    constexpr int HOUT = HIN * 2;
    static_assert(HIN == 2 * TW, "HIN must equal 2*TW");
    static_assert(TH * TW == 128, "block must be 128 threads");
    static_assert(COB % 4 == 0, "COB multiple of 4");
    __shared__ __align__(16) float ws[CISTEP * 9 * COB];   // [ci][k][co]

    const int n   = blockIdx.y;
    const int cob = blockIdx.z * COB;
    const int tid = threadIdx.x;
    const int ty  = tid / TW;
    const int tx  = tid % TW;
    const int a   = blockIdx.x * TH + ty;
    const int b0  = tx;
    const int b1  = tx + TW;

    const float* inB = in + (size_t)n * CIN * HIN * HIN;
    constexpr size_t HH = (size_t)HIN * HIN;

    // acc2[p][c2][q]
    u64 acc2[2][COB / 2][4];
#pragma unroll
    for (int p = 0; p < 2; p++)
#pragma unroll
        for (int i = 0; i < COB / 2; i++)
#pragma unroll
            for (int q = 0; q < 4; q++) acc2[p][i][q] = 0ull;

    const bool aOK  = (a + 1 < HIN);
    const bool bOK1 = (b1 + 1 < HIN);

    for (int ci0 = 0; ci0 < CIN; ci0 += CISTEP) {
        __syncthreads();
        for (int i = tid; i < COB * CISTEP * 9; i += 128) {
            int co = i % COB;
            int r  = i / COB;
            int k  = r % 9;
            int ci = r / 9;
            ws[(ci * 9 + k) * COB + co] =
                w[(size_t)(cob + co) * CIN * 9 + (size_t)(ci0 + ci) * 9 + k];
        }
        __syncthreads();

#pragma unroll 2
        for (int ci = 0; ci < CISTEP; ci++) {
            const float* p0 = inB + (size_t)(ci0 + ci) * HH + (size_t)a * HIN + b0;
            const float* p1 = p0 + TW;
            float a00 = __ldg(p0);
            float a01 = __ldg(p0 + 1);
            float a10 = aOK ? __ldg(p0 + HIN) : 0.f;
            float a11 = aOK ? __ldg(p0 + HIN + 1) : 0.f;
            float c00 = __ldg(p1);
            float c01 = bOK1 ? __ldg(p1 + 1) : 0.f;
            float c10 = aOK ? __ldg(p1 + HIN) : 0.f;
            float c11 = (aOK && bOK1) ? __ldg(p1 + HIN + 1) : 0.f;
            u64 a00d = pack2(a00, a00), a01d = pack2(a01, a01);
            u64 a10d = pack2(a10, a10), a11d = pack2(a11, a11);
            u64 c00d = pack2(c00, c00), c01d = pack2(c01, c01);
            u64 c10d = pack2(c10, c10), c11d = pack2(c11, c11);
            const float4* wb4 = reinterpret_cast<const float4*>(&ws[ci * 9 * COB]);
#pragma unroll
            for (int c4 = 0; c4 < COB / 4; c4++) {
                // load 9 taps x 4 co
                u64 wp[9][2];
#pragma unroll
                for (int k = 0; k < 9; k++) {
                    float4 wv = wb4[k * (COB / 4) + c4];
                    wp[k][0] = pack2(wv.x, wv.y);
                    wp[k][1] = pack2(wv.z, wv.w);
                }
#pragma unroll
                for (int h = 0; h < 2; h++) {
                    int c2 = c4 * 2 + h;
                    FFMA2(acc2[0][c2][0], a00d, wp[4][h]);
                    FFMA2(acc2[0][c2][1], a01d, wp[5][h]);
                    FFMA2(acc2[0][c2][1], a00d, wp[3][h]);
                    FFMA2(acc2[0][c2][2], a10d, wp[7][h]);
                    FFMA2(acc2[0][c2][2], a00d, wp[1][h]);
                    FFMA2(acc2[0][c2][3], a11d, wp[8][h]);
                    FFMA2(acc2[0][c2][3], a10d, wp[6][h]);
                    FFMA2(acc2[0][c2][3], a01d, wp[2][h]);
                    FFMA2(acc2[0][c2][3], a00d, wp[0][h]);
                    FFMA2(acc2[1][c2][0], c00d, wp[4][h]);
                    FFMA2(acc2[1][c2][1], c01d, wp[5][h]);
                    FFMA2(acc2[1][c2][1], c00d, wp[3][h]);
                    FFMA2(acc2[1][c2][2], c10d, wp[7][h]);
                    FFMA2(acc2[1][c2][2], c00d, wp[1][h]);
                    FFMA2(acc2[1][c2][3], c11d, wp[8][h]);
                    FFMA2(acc2[1][c2][3], c10d, wp[6][h]);
                    FFMA2(acc2[1][c2][3], c01d, wp[2][h]);
                    FFMA2(acc2[1][c2][3], c00d, wp[0][h]);
                }
            }
        }
    }

#pragma unroll
    for (int p = 0; p < 2; p++) {
        int b = (p == 0) ? b0 : b1;
#pragma unroll
        for (int c2 = 0; c2 < COB / 2; c2++) {
            float2 q0 = unpack2(acc2[p][c2][0]);
            float2 q1 = unpack2(acc2[p][c2][1]);
            float2 q2 = unpack2(acc2[p][c2][2]);
            float2 q3 = unpack2(acc2[p][c2][3]);
            float r0a, r1a, r2a, r3a, r0b, r1b, r2b, r3b;
            if (ACT == 0) {
                r0a = fmaxf(q0.x, 0.f); r1a = fmaxf(q1.x, 0.f);
                r2a = fmaxf(q2.x, 0.f); r3a = fmaxf(q3.x, 0.f);
                r0b = fmaxf(q0.y, 0.f); r1b = fmaxf(q1.y, 0.f);
                r2b = fmaxf(q2.y, 0.f); r3b = fmaxf(q3.y, 0.f);
            } else {
                r0a = 1.f / (1.f + expf(-q0.x)); r1a = 1.f / (1.f + expf(-q1.x));
                r2a = 1.f / (1.f + expf(-q2.x)); r3a = 1.f / (1.f + expf(-q3.x));
                r0b = 1.f / (1.f + expf(-q0.y)); r1b = 1.f / (1.f + expf(-q1.y));
                r2b = 1.f / (1.f + expf(-q2.y)); r3b = 1.f / (1.f + expf(-q3.y));
            }
            float* oa = out + ((size_t)n * COUT + cob + 2 * c2) * HOUT * HOUT +
                        (size_t)(2 * a) * HOUT + 2 * b;
            float* ob = oa + (size_t)HOUT * HOUT;
            *reinterpret_cast<float2*>(oa)        = make_float2(r0a, r1a);
            *reinterpret_cast<float2*>(oa + HOUT) = make_float2(r2a, r3a);
            *reinterpret_cast<float2*>(ob)        = make_float2(r0b, r1b);
            *reinterpret_cast<float2*>(ob + HOUT) = make_float2(r2b, r3b);
        }
    }
}

// ---------------------------------------------------------------------------
// Scalar padded deconv (COUT=3 final layer), R15 version.
// ---------------------------------------------------------------------------
template <int CIN, int COUT, int HIN, int COB, int TH, int TW, int CISTEP, int ACT>
__global__ void __launch_bounds__(128) deconv_s2_p2(const float* __restrict__ in,
                                                    const float* __restrict__ w,
                                                    float* __restrict__ out) {
    constexpr int HOUT = HIN * 2;
    static_assert(HIN == 2 * TW, "HIN must equal 2*TW");
    __shared__ __align__(16) float ws[COB * CISTEP * 12];

    const int n   = blockIdx.y;
    const int cob = blockIdx.z * COB;
    const int tid = threadIdx.x;
    const int ty  = tid / TW;
    const int tx  = tid % TW;
    const int a   = blockIdx.x * TH + ty;
    const int b0  = tx;
    const int b1  = tx + TW;

    const float* inB = in + (size_t)n * CIN * HIN * HIN;
    constexpr size_t HH = (size_t)HIN * HIN;

    float acc[2][COB][4];
#pragma unroll
    for (int p = 0; p < 2; p++)
#pragma unroll
        for (int i = 0; i < COB; i++)
#pragma unroll
            for (int q = 0; q < 4; q++) acc[p][i][q] = 0.f;

    const bool aOK  = (a + 1 < HIN);
    const bool bOK1 = (b1 + 1 < HIN);

    for (int ci0 = 0; ci0 < CIN; ci0 += CISTEP) {
        __syncthreads();
        for (int i = tid; i < COB * CISTEP * 9; i += 128) {
            int co = i / (CISTEP * 9);
            int r  = i % (CISTEP * 9);
            int ci = r / 9;
            int k  = r % 9;
            ws[(co * CISTEP + ci) * 12 + k] =
                w[(size_t)(cob + co) * CIN * 9 + (size_t)(ci0 + ci) * 9 + k];
        }
        __syncthreads();

#pragma unroll
        for (int ci = 0; ci < CISTEP; ci++) {
            const float* p0 = inB + (size_t)(ci0 + ci) * HH + (size_t)a * HIN + b0;
            const float* p1 = p0 + TW;
            float a00 = __ldg(p0);
            float a01 = __ldg(p0 + 1);
            float a10 = aOK ? __ldg(p0 + HIN) : 0.f;
            float a11 = aOK ? __ldg(p0 + HIN + 1) : 0.f;
            float c00 = __ldg(p1);
            float c01 = bOK1 ? __ldg(p1 + 1) : 0.f;
            float c10 = aOK ? __ldg(p1 + HIN) : 0.f;
            float c11 = (aOK && bOK1) ? __ldg(p1 + HIN + 1) : 0.f;
#pragma unroll
            for (int co = 0; co < COB; co++) {
                const float4* wp = reinterpret_cast<const float4*>(
                    &ws[(co * CISTEP + ci) * 12]);
                float4 wA = wp[0];
                float4 wB = wp[1];
                float4 wC = wp[2];
                acc[0][co][0] = fmaf(a00, wB.x, acc[0][co][0]);
                acc[0][co][1] = fmaf(a00, wA.w, fmaf(a01, wB.y, acc[0][co][1]));
                acc[0][co][2] = fmaf(a00, wA.y, fmaf(a10, wB.w, acc[0][co][2]));
                acc[0][co][3] = fmaf(a00, wA.x, fmaf(a01, wA.z,
                                fmaf(a10, wB.z, fmaf(a11, wC.x, acc[0][co][3]))));
                acc[1][co][0] = fmaf(c00, wB.x, acc[1][co][0]);
                acc[1][co][1] = fmaf(c00, wA.w, fmaf(c01, wB.y, acc[1][co][1]));
                acc[1][co][2] = fmaf(c00, wA.y, fmaf(c10, wB.w, acc[1][co][2]));
                acc[1][co][3] = fmaf(c00, wA.x, fmaf(c01, wA.z,
                                fmaf(c10, wB.z, fmaf(c11, wC.x, acc[1][co][3]))));
            }
        }
    }

#pragma unroll
    for (int p = 0; p < 2; p++) {
        int b = (p == 0) ? b0 : b1;
#pragma unroll
        for (int co = 0; co < COB; co++) {
            float r0, r1, r2, r3;
            if (ACT == 0) {
                r0 = fmaxf(acc[p][co][0], 0.f);
                r1 = fmaxf(acc[p][co][1], 0.f);
                r2 = fmaxf(acc[p][co][2], 0.f);
                r3 = fmaxf(acc[p][co][3], 0.f);
            } else {
                r0 = 1.f / (1.f + expf(-acc[p][co][0]));
                r1 = 1.f / (1.f + expf(-acc[p][co][1]));
                r2 = 1.f / (1.f + expf(-acc[p][co][2]));
                r3 = 1.f / (1.f + expf(-acc[p][co][3]));
            }
            float* o = out + ((size_t)n * COUT + cob + co) * HOUT * HOUT +
                       (size_t)(2 * a) * HOUT + 2 * b;
            *reinterpret_cast<float2*>(o)        = make_float2(r0, r1);
            *reinterpret_cast<float2*>(o + HOUT) = make_float2(r2, r3);
        }
    }
}

// ---------------------------------------------------------------------------
// XLA GPU row-reduction emulation for 256 elements (FROZEN).
// ---------------------------------------------------------------------------
template <typename F>
__device__ __forceinline__ float xla_reduce256(F f) {
    float v[32];
#pragma unroll
    for (int l = 0; l < 32; l++) {
        float s = f(l);
#pragma unroll
        for (int i = 1; i < 8; i++) s = __fadd_rn(s, f(l + 32 * i));
        v[l] = s;
    }
    for (int off = 16; off; off >>= 1)
        for (int l = 0; l < off; l++) v[l] = __fadd_rn(v[l], v[l + off]);
    return v[0];
}

// ---------------------------------------------------------------------------
// Codebook prep (FROZEN arithmetic).
// ---------------------------------------------------------------------------
__global__ void cb_t_kernel(const float* __restrict__ cb) {
    int i = blockIdx.x * 256 + threadIdx.x;
    int d = i >> 10;
    int c = i & 1023;
    g_ct[i] = cb[(size_t)c * 256 + d];
}

__global__ void cb_norm_kernel(const float* __restrict__ cb) {
    int code = blockIdx.x * blockDim.x + threadIdx.x;
    if (code >= 1024) return;
    const float* r = cb + (size_t)code * 256;
    double sd = 0.0;
    for (int d = 0; d < 256; d++) {
        float v = r[d];
        sd = fma((double)v, (double)v, sd);
    }
    g_cnorm_d[code] = sd;
    g_cnorm_f[code] = xla_reduce256([&](int i) { return __fmul_rn(r[i], r[i]); });
}

__global__ void reset_flags_kernel() {
    if (threadIdx.x == 0) g_nflag = 0;
}

__device__ __forceinline__ void top2_merge(long long& b1, long long& b2,
                                           long long o1, long long o2) {
    if (o1 < b1) {
        b2 = (b1 < o2) ? b1 : o2;
        b1 = o1;
    } else {
        b2 = (b2 < o1) ? b2 : o1;
    }
}

// ---------------------------------------------------------------------------
// VQ phase A: GEMM via FFMA2 (j-paired; per-(v,j) chains bit-identical).
// Keys on the ulp(znorm) grid; flags near-tie / binade-edge rows for phase B.
// ---------------------------------------------------------------------------
__global__ void __launch_bounds__(128) vq_kernel(const float* __restrict__ z,
                                                 float* __restrict__ ids_f) {
    constexpr int V = 16;
    constexpr long long LLMAX = 0x7fffffffffffffffLL;
    __shared__ float zs[256 * V];
    __shared__ double invu_s[V];
    __shared__ int   bflag_s[V];
    __shared__ long long red1[4 * V];
    __shared__ long long red2[4 * V];

    const int tid = threadIdx.x;
    const int blk = blockIdx.x;          // 2048 blocks
    const int n   = blk >> 6;
    const int hw0 = (blk & 63) * V;
    const float* zb = z + (size_t)n * 256 * 1024 + hw0;

    for (int i = tid; i < V * 256; i += 128) {
        int v = i & 15;
        int d = i >> 4;
        zs[(d << 4) + v] = zb[(size_t)d * 1024 + v];
    }
    __syncthreads();

    if (tid < V) {
        float s = 0.f;
        for (int d = 0; d < 256; d++) {
            float zd = zs[(d << 4) + tid];
            s = __fadd_rn(s, __fmul_rn(zd, zd));
        }
        int e;
        frexpf(s, &e);
        invu_s[tid] = ldexp(1.0, 24 - e);
        float lo = ldexpf(1.0f, e - 1);
        float hi = ldexpf(1.0f, e);
        bflag_s[tid] = ((s - lo) < 0.006f * s) || ((hi - s) < 3e-5f * hi);
    }
    __syncthreads();

    // acc2[v][jp]: codes (8*tid + 2*jp, 8*tid + 2*jp + 1)
    u64 acc2[V][4];
#pragma unroll
    for (int v = 0; v < V; v++)
#pragma unroll
        for (int j = 0; j < 4; j++) acc2[v][j] = 0ull;

    const float4* ctp = reinterpret_cast<const float4*>(g_ct) + tid * 2;
#pragma unroll 2
    for (int d = 0; d < 256; d++) {
        float4 c0 = __ldg(ctp + (size_t)d * 256);
        float4 c1 = __ldg(ctp + (size_t)d * 256 + 1);
        u64 cp[4] = {pack2(c0.x, c0.y), pack2(c0.z, c0.w),
                     pack2(c1.x, c1.y), pack2(c1.z, c1.w)};
#pragma unroll
        for (int v = 0; v < V; v++) {
            float zd = zs[(d << 4) + v];
            u64 zdd = pack2(zd, zd);
#pragma unroll
            for (int j = 0; j < 4; j++) FFMA2(acc2[v][j], zdd, cp[j]);
        }
    }

    double cnd[8];
#pragma unroll
    for (int j = 0; j < 8; j++) cnd[j] = g_cnorm_d[tid * 8 + j];

    const int lane = tid & 31;
    const int warp = tid >> 5;

#pragma unroll
    for (int v = 0; v < V; v++) {
        double invu = invu_s[v];
        long long b1 = LLMAX, b2 = LLMAX;
#pragma unroll
        for (int jp = 0; jp < 4; jp++) {
            float2 av = unpack2(acc2[v][jp]);
#pragma unroll
            for (int h = 0; h < 2; h++) {
                int j = jp * 2 + h;
                double p = 2.0 * (double)((h == 0) ? av.x : av.y);
                long long key = llrint(cnd[j] * invu) - llrint(p * invu);
                long long pk = (key << 10) | (long long)(tid * 8 + j);
                if (pk < b1) { b2 = b1; b1 = pk; }
                else if (pk < b2) { b2 = pk; }
            }
        }
#pragma unroll
        for (int off = 16; off; off >>= 1) {
            long long o1 = __shfl_xor_sync(0xffffffffu, b1, off);
            long long o2 = __shfl_xor_sync(0xffffffffu, b2, off);
            top2_merge(b1, b2, o1, o2);
        }
        if (lane == 0) { red1[warp * V + v] = b1; red2[warp * V + v] = b2; }
    }
    __syncthreads();

    if (tid < V) {
        long long b1 = red1[tid], b2 = red2[tid];
#pragma unroll
        for (int w = 1; w < 4; w++) top2_merge(b1, b2, red1[w * V + tid], red2[w * V + tid]);
        int id  = (int)(b1 & 1023);
        int row = n * 1024 + hw0 + tid;
        g_ids[row] = id;
        ids_f[row] = (float)id;
        long long margin = (b2 >> 10) - (b1 >> 10);
        if (margin <= 24 || bflag_s[tid]) {
            int slot = atomicAdd(&g_nflag, 1);
            if (slot < 16384) g_flagrows[slot] = row;
        }
    }
}

// ---------------------------------------------------------------------------
// VQ phase B (FROZEN arithmetic).
// ---------------------------------------------------------------------------
__global__ void __launch_bounds__(256) vq_fix_kernel(const float* __restrict__ z,
                                                     float* __restrict__ ids_f) {
    int nf = g_nflag;
    if (nf > 16384) nf = 16384;
    if ((int)blockIdx.x >= nf) return;
    const int row = g_flagrows[blockIdx.x];
    const int n = row >> 10;
    const int hw = row & 1023;
    const int t = threadIdx.x;

    __shared__ float zsh[256];
    __shared__ float znf_sh;
    __shared__ unsigned long long redp[8];

    zsh[t] = z[((size_t)n * 256 + t) * 1024 + hw];
    __syncthreads();

    if (t == 0) {
        znf_sh = xla_reduce256([&](int i) { return __fmul_rn(zsh[i], zsh[i]); });
    }
    __syncthreads();
    const float znf = znf_sh;

    unsigned long long best = 0xffffffffffffffffULL;
#pragma unroll
    for (int q = 0; q < 4; q++) {
        int j = t + 256 * q;
        float a = 0.f;
        for (int d = 0; d < 256; d++)
            a = fmaf(2.0f * zsh[d], g_ct[d * 1024 + j], a);
        float s1 = __fadd_rn(znf, -a);
        float dj = __fadd_rn(s1, g_cnorm_f[j]);
        unsigned bb  = __float_as_uint(dj);
        unsigned key = (bb & 0x80000000u) ? ~bb : (bb | 0x80000000u);
        unsigned long long pk = ((unsigned long long)key << 32) | (unsigned)j;
        if (pk < best) best = pk;
    }
#pragma unroll
    for (int off = 16; off; off >>= 1) {
        unsigned long long o = __shfl_xor_sync(0xffffffffu, best, off);
        if (o < best) best = o;
    }
    if ((t & 31) == 0) redp[t >> 5] = best;
    __syncthreads();
    if (t == 0) {
        unsigned long long b = redp[0];
#pragma unroll
        for (int w = 1; w < 8; w++) if (redp[w] < b) b = redp[w];
        int id = (int)(b & 0xffffffffu);
        g_ids[row] = id;
        ids_f[row] = (float)id;
    }
}

// e_k[n][c][hw] = codebook[ids[n][hw]][c]
__global__ void ek_kernel(const float* __restrict__ cb, float* __restrict__ ek) {
    size_t i = (size_t)blockIdx.x * 256 + threadIdx.x;
    int hw = (int)(i & 1023);
    int c  = (int)((i >> 10) & 255);
    int n  = (int)(i >> 18);
    int id = g_ids[n * 1024 + hw];
    ek[i] = cb[(size_t)id * 256 + c];
}

// ---------------------------------------------------------------------------
extern "C" void kernel_launch(void* const* d_in, const int* in_sizes, int n_in,
                              void* d_out, int out_size) {
    const float* x   = (const float*)d_in[0];
    const float* ew0 = (const float*)d_in[1];
    const float* ew1 = (const float*)d_in[2];
    const float* ew2 = (const float*)d_in[3];
    const float* cb  = (const float*)d_in[4];
    const float* dw0 = (const float*)d_in[5];
    const float* dw1 = (const float*)d_in[6];
    const float* dw2 = (const float*)d_in[7];
    float* out = (float*)d_out;

    float* bufA = nullptr;
    float* bufB = nullptr;
    cudaGetSymbolAddress((void**)&bufA, g_bufA);
    cudaGetSymbolAddress((void**)&bufB, g_bufB);

    // encoder (frozen per-output accumulation order; FFMA2 co-pairs)
    conv_s2_p2x<3, 64, 256, 16, 2, 64, true><<<dim3(64, 32, 4), 128>>>(x, ew0, bufA);
    conv_s2_p2x<64, 128, 128, 16, 4, 32, true><<<dim3(16, 32, 8), 128>>>(bufA, ew1, bufB);
    conv_s2_p2x<128, 256, 64, 8, 8, 16, false><<<dim3(4, 32, 32), 128>>>(bufB, ew2, out + Z_OFF);

    // VQ
    cb_t_kernel<<<1024, 256>>>(cb);
    cb_norm_kernel<<<4, 256>>>(cb);
    reset_flags_kernel<<<1, 32>>>();
    vq_kernel<<<2048, 128>>>(out + Z_OFF, out + IDS_OFF);
    vq_fix_kernel<<<16384, 256>>>(out + Z_OFF, out + IDS_OFF);
    ek_kernel<<<32768, 256>>>(cb, out + EK_OFF);

    // decoder (FFMA2 co-pairs; final layer scalar)
    deconv_s2_p2x<256, 128, 32, 8, 8, 16, 8, 0><<<dim3(4, 32, 16), 128>>>(out + EK_OFF, dw0, bufB);
    deconv_s2_p2x<128, 64, 64, 8, 4, 32, 8, 0><<<dim3(16, 32, 8), 128>>>(bufB, dw1, bufA);
    deconv_s2_p2<64, 3, 128, 3, 2, 64, 8, 1><<<dim3(64, 32, 1), 128>>>(bufA, dw2, out + OUT_OFF);
}